// round 1
// baseline (speedup 1.0000x reference)
#include <cuda_runtime.h>
#include <cuda_bf16.h>

// Scratch for Q, K, V projections: [B*T, H] = [8192, 64] fp32 each.
__device__ float g_q[8192 * 64];
__device__ float g_k[8192 * 64];
__device__ float g_v[8192 * 64];

#define D_IN 1024
#define H_SZ 64
#define M_TOT 8192   // B*T
#define T_SEQ 2048
#define B_SZ 4

// ---------------------------------------------------------------------------
// Kernel 1: fused QKV projection.  out{q,k,v}[m, :64] = x[m, :1024] @ W{q,k,v}
// Block: 256 threads, tile M=64 rows x N=64 cols (all of H) for 3 weight mats.
// Each thread: 4x4 microtile per W -> 48 fp32 accumulators.
// ---------------------------------------------------------------------------
__global__ __launch_bounds__(256) void qkv_kernel(
    const float* __restrict__ x,
    const float* __restrict__ Wq,
    const float* __restrict__ Wk,
    const float* __restrict__ Wv)
{
    __shared__ __align__(16) float xs[64][33];      // x tile, padded (bank-safe)
    __shared__ __align__(16) float Ws[3][32][64];   // 3 weight tiles [k][n]

    const int tid = threadIdx.x;
    const int m0  = blockIdx.x * 64;
    const int tx  = tid & 15;
    const int ty  = tid >> 4;
    const int r0  = ty * 4;
    const int c0  = tx * 4;

    float acc[3][4][4];
    #pragma unroll
    for (int w = 0; w < 3; w++)
        #pragma unroll
        for (int j = 0; j < 4; j++)
            #pragma unroll
            for (int i = 0; i < 4; i++)
                acc[w][j][i] = 0.0f;

    for (int k0 = 0; k0 < D_IN; k0 += 32) {
        __syncthreads();
        // Load x tile: 64 rows x 32 k. 512 float4, 2 per thread.
        {
            const int row = tid >> 3;     // 0..31
            const int k4  = tid & 7;      // 0..7
            #pragma unroll
            for (int p = 0; p < 2; p++) {
                const int m = row + p * 32;
                float4 vx = *(const float4*)&x[(m0 + m) * D_IN + k0 + k4 * 4];
                xs[m][k4 * 4 + 0] = vx.x;
                xs[m][k4 * 4 + 1] = vx.y;
                xs[m][k4 * 4 + 2] = vx.z;
                xs[m][k4 * 4 + 3] = vx.w;
            }
        }
        // Load W tiles: per W, 32 rows x 64 cols = 512 float4, 2 per thread.
        #pragma unroll
        for (int w = 0; w < 3; w++) {
            const float* Wp = (w == 0) ? Wq : ((w == 1) ? Wk : Wv);
            #pragma unroll
            for (int p = 0; p < 2; p++) {
                const int idx = tid + p * 256;
                const int kk  = idx >> 4;   // 0..31
                const int c4  = idx & 15;   // 0..15
                float4 wv = *(const float4*)&Wp[(k0 + kk) * H_SZ + c4 * 4];
                *(float4*)&Ws[w][kk][c4 * 4] = wv;
            }
        }
        __syncthreads();

        #pragma unroll 8
        for (int kk = 0; kk < 32; kk++) {
            float xr[4];
            #pragma unroll
            for (int j = 0; j < 4; j++) xr[j] = xs[r0 + j][kk];
            #pragma unroll
            for (int w = 0; w < 3; w++) {
                float4 wv = *(const float4*)&Ws[w][kk][c0];
                #pragma unroll
                for (int j = 0; j < 4; j++) {
                    acc[w][j][0] += xr[j] * wv.x;
                    acc[w][j][1] += xr[j] * wv.y;
                    acc[w][j][2] += xr[j] * wv.z;
                    acc[w][j][3] += xr[j] * wv.w;
                }
            }
        }
    }

    // Write q, k, v
    #pragma unroll
    for (int w = 0; w < 3; w++) {
        float* outp = (w == 0) ? g_q : ((w == 1) ? g_k : g_v);
        #pragma unroll
        for (int j = 0; j < 4; j++) {
            float4 o;
            o.x = acc[w][j][0]; o.y = acc[w][j][1];
            o.z = acc[w][j][2]; o.w = acc[w][j][3];
            *(float4*)&outp[(m0 + r0 + j) * H_SZ + c0] = o;
        }
    }
}

// ---------------------------------------------------------------------------
// Kernel 2: causal flash attention (fp32, online softmax).
// Grid: (qtile=T/64, B). Block: 256 threads, BQ=BK=64, H=64.
// Thread layout 16x16; each thread owns 4 rows x 4 cols microtiles.
// ---------------------------------------------------------------------------
__global__ __launch_bounds__(256) void attn_kernel(float* __restrict__ out)
{
    __shared__ __align__(16) float Qs[64 * 65];   // [r][h], padded
    __shared__ __align__(16) float Kt[64 * 65];   // [h][c], padded (transposed)
    __shared__ __align__(16) float Vs[64 * 64];   // [s][h]
    __shared__ __align__(16) float Pt[64 * 65];   // [s][r], padded (transposed)

    const int tid = threadIdx.x;
    const int b   = blockIdx.y;
    const int qt  = blockIdx.x;
    const int q_base = qt * 64;

    const float* qb = g_q + b * T_SEQ * H_SZ;
    const float* kb = g_k + b * T_SEQ * H_SZ;
    const float* vb = g_v + b * T_SEQ * H_SZ;

    const int tx = tid & 15;
    const int ty = tid >> 4;
    const int r0 = ty * 4;
    const int c0 = tx * 4;

    // Load Q tile (once): 64 rows x 64 h. 1024 float4, 4 per thread.
    #pragma unroll
    for (int p = 0; p < 4; p++) {
        const int idx = tid + p * 256;
        const int r   = idx >> 4;
        const int h4  = idx & 15;
        float4 t = *(const float4*)&qb[(q_base + r) * H_SZ + h4 * 4];
        Qs[r * 65 + h4 * 4 + 0] = t.x;
        Qs[r * 65 + h4 * 4 + 1] = t.y;
        Qs[r * 65 + h4 * 4 + 2] = t.z;
        Qs[r * 65 + h4 * 4 + 3] = t.w;
    }

    float m_old[4], l[4], o[4][4];
    #pragma unroll
    for (int j = 0; j < 4; j++) {
        m_old[j] = -1e30f;
        l[j] = 0.0f;
        #pragma unroll
        for (int i = 0; i < 4; i++) o[j][i] = 0.0f;
    }
    __syncthreads();

    const int ntile = qt + 1;
    for (int t = 0; t < ntile; t++) {
        const int k_base = t * 64;
        __syncthreads();  // prior GEMM2 done before overwriting Kt/Vs
        // Load K (transposed) and V tiles: 4 float4 pairs per thread.
        #pragma unroll
        for (int p = 0; p < 4; p++) {
            const int idx = tid + p * 256;
            const int c   = idx >> 4;
            const int h4  = idx & 15;
            float4 kv4 = *(const float4*)&kb[(k_base + c) * H_SZ + h4 * 4];
            Kt[(h4 * 4 + 0) * 65 + c] = kv4.x;
            Kt[(h4 * 4 + 1) * 65 + c] = kv4.y;
            Kt[(h4 * 4 + 2) * 65 + c] = kv4.z;
            Kt[(h4 * 4 + 3) * 65 + c] = kv4.w;
            float4 vv4 = *(const float4*)&vb[(k_base + c) * H_SZ + h4 * 4];
            *(float4*)&Vs[c * 64 + h4 * 4] = vv4;
        }
        __syncthreads();

        // GEMM1: S = Q K^T  (4x4 microtile)
        float s[4][4];
        #pragma unroll
        for (int j = 0; j < 4; j++)
            #pragma unroll
            for (int i = 0; i < 4; i++) s[j][i] = 0.0f;

        #pragma unroll 8
        for (int h = 0; h < 64; h++) {
            float qv[4], kv[4];
            #pragma unroll
            for (int j = 0; j < 4; j++) qv[j] = Qs[(r0 + j) * 65 + h];
            #pragma unroll
            for (int i = 0; i < 4; i++) kv[i] = Kt[h * 65 + c0 + i];
            #pragma unroll
            for (int j = 0; j < 4; j++)
                #pragma unroll
                for (int i = 0; i < 4; i++) s[j][i] += qv[j] * kv[i];
        }

        // Scale + causal mask (only diagonal tile needs mask).
        const float scale = 0.125f;  // 64^-0.5
        if (t == qt) {
            #pragma unroll
            for (int j = 0; j < 4; j++)
                #pragma unroll
                for (int i = 0; i < 4; i++) {
                    const int qg = r0 + j;
                    const int kg = c0 + i;
                    s[j][i] = (kg <= qg) ? s[j][i] * scale : -1e30f;
                }
        } else {
            #pragma unroll
            for (int j = 0; j < 4; j++)
                #pragma unroll
                for (int i = 0; i < 4; i++) s[j][i] *= scale;
        }

        // Row max (reduce across the 16 lanes sharing a row group).
        float mt[4];
        #pragma unroll
        for (int j = 0; j < 4; j++) {
            mt[j] = fmaxf(fmaxf(s[j][0], s[j][1]), fmaxf(s[j][2], s[j][3]));
        }
        #pragma unroll
        for (int off = 1; off < 16; off <<= 1)
            #pragma unroll
            for (int j = 0; j < 4; j++)
                mt[j] = fmaxf(mt[j], __shfl_xor_sync(0xffffffffu, mt[j], off));

        float alpha[4], psum[4];
        #pragma unroll
        for (int j = 0; j < 4; j++) {
            const float mnew = fmaxf(m_old[j], mt[j]);
            alpha[j] = __expf(m_old[j] - mnew);
            m_old[j] = mnew;
            psum[j] = 0.0f;
            #pragma unroll
            for (int i = 0; i < 4; i++) {
                s[j][i] = __expf(s[j][i] - mnew);
                psum[j] += s[j][i];
            }
        }
        #pragma unroll
        for (int off = 1; off < 16; off <<= 1)
            #pragma unroll
            for (int j = 0; j < 4; j++)
                psum[j] += __shfl_xor_sync(0xffffffffu, psum[j], off);
        #pragma unroll
        for (int j = 0; j < 4; j++) {
            l[j] = l[j] * alpha[j] + psum[j];
            #pragma unroll
            for (int i = 0; i < 4; i++) o[j][i] *= alpha[j];
        }

        // Write P transposed to smem: Pt[s][r]
        #pragma unroll
        for (int i = 0; i < 4; i++)
            #pragma unroll
            for (int j = 0; j < 4; j++)
                Pt[(c0 + i) * 65 + (r0 + j)] = s[j][i];
        __syncthreads();

        // GEMM2: O += P V
        #pragma unroll 8
        for (int ss = 0; ss < 64; ss++) {
            float pv[4];
            #pragma unroll
            for (int j = 0; j < 4; j++) pv[j] = Pt[ss * 65 + r0 + j];
            float4 vv = *(const float4*)&Vs[ss * 64 + c0];
            #pragma unroll
            for (int j = 0; j < 4; j++) {
                o[j][0] += pv[j] * vv.x;
                o[j][1] += pv[j] * vv.y;
                o[j][2] += pv[j] * vv.z;
                o[j][3] += pv[j] * vv.w;
            }
        }
    }

    // Epilogue: normalize and store
    float* ob = out + b * T_SEQ * H_SZ;
    #pragma unroll
    for (int j = 0; j < 4; j++) {
        const float inv_l = 1.0f / l[j];
        float4 t;
        t.x = o[j][0] * inv_l;
        t.y = o[j][1] * inv_l;
        t.z = o[j][2] * inv_l;
        t.w = o[j][3] * inv_l;
        *(float4*)&ob[(q_base + r0 + j) * H_SZ + c0] = t;
    }
}

extern "C" void kernel_launch(void* const* d_in, const int* in_sizes, int n_in,
                              void* d_out, int out_size)
{
    const float* x  = (const float*)d_in[0];
    const float* Wq = (const float*)d_in[1];
    const float* Wk = (const float*)d_in[2];
    const float* Wv = (const float*)d_in[3];
    float* out = (float*)d_out;

    qkv_kernel<<<M_TOT / 64, 256>>>(x, Wq, Wk, Wv);
    attn_kernel<<<dim3(T_SEQ / 64, B_SZ), 256>>>(out);
}

// round 2
// speedup vs baseline: 1.0817x; 1.0817x over previous
#include <cuda_runtime.h>
#include <cuda_bf16.h>

// Scratch for Q, K, V projections: [B*T, H] = [8192, 64] fp32 each.
__device__ float g_q[8192 * 64];
__device__ float g_k[8192 * 64];
__device__ float g_v[8192 * 64];

#define D_IN 1024
#define H_SZ 64
#define M_TOT 8192   // B*T
#define T_SEQ 2048
#define B_SZ 4

// ---------------------------------------------------------------------------
// Kernel 1: fused QKV projection (unchanged — near fp32 FFMA roofline).
// ---------------------------------------------------------------------------
__global__ __launch_bounds__(256) void qkv_kernel(
    const float* __restrict__ x,
    const float* __restrict__ Wq,
    const float* __restrict__ Wk,
    const float* __restrict__ Wv)
{
    __shared__ __align__(16) float xs[64][33];
    __shared__ __align__(16) float Ws[3][32][64];

    const int tid = threadIdx.x;
    const int m0  = blockIdx.x * 64;
    const int tx  = tid & 15;
    const int ty  = tid >> 4;
    const int r0  = ty * 4;
    const int c0  = tx * 4;

    float acc[3][4][4];
    #pragma unroll
    for (int w = 0; w < 3; w++)
        #pragma unroll
        for (int j = 0; j < 4; j++)
            #pragma unroll
            for (int i = 0; i < 4; i++)
                acc[w][j][i] = 0.0f;

    for (int k0 = 0; k0 < D_IN; k0 += 32) {
        __syncthreads();
        {
            const int row = tid >> 3;
            const int k4  = tid & 7;
            #pragma unroll
            for (int p = 0; p < 2; p++) {
                const int m = row + p * 32;
                float4 vx = *(const float4*)&x[(m0 + m) * D_IN + k0 + k4 * 4];
                xs[m][k4 * 4 + 0] = vx.x;
                xs[m][k4 * 4 + 1] = vx.y;
                xs[m][k4 * 4 + 2] = vx.z;
                xs[m][k4 * 4 + 3] = vx.w;
            }
        }
        #pragma unroll
        for (int w = 0; w < 3; w++) {
            const float* Wp = (w == 0) ? Wq : ((w == 1) ? Wk : Wv);
            #pragma unroll
            for (int p = 0; p < 2; p++) {
                const int idx = tid + p * 256;
                const int kk  = idx >> 4;
                const int c4  = idx & 15;
                float4 wv = *(const float4*)&Wp[(k0 + kk) * H_SZ + c4 * 4];
                *(float4*)&Ws[w][kk][c4 * 4] = wv;
            }
        }
        __syncthreads();

        #pragma unroll 8
        for (int kk = 0; kk < 32; kk++) {
            float xr[4];
            #pragma unroll
            for (int j = 0; j < 4; j++) xr[j] = xs[r0 + j][kk];
            #pragma unroll
            for (int w = 0; w < 3; w++) {
                float4 wv = *(const float4*)&Ws[w][kk][c0];
                #pragma unroll
                for (int j = 0; j < 4; j++) {
                    acc[w][j][0] += xr[j] * wv.x;
                    acc[w][j][1] += xr[j] * wv.y;
                    acc[w][j][2] += xr[j] * wv.z;
                    acc[w][j][3] += xr[j] * wv.w;
                }
            }
        }
    }

    #pragma unroll
    for (int w = 0; w < 3; w++) {
        float* outp = (w == 0) ? g_q : ((w == 1) ? g_k : g_v);
        #pragma unroll
        for (int j = 0; j < 4; j++) {
            float4 o;
            o.x = acc[w][j][0]; o.y = acc[w][j][1];
            o.z = acc[w][j][2]; o.w = acc[w][j][3];
            *(float4*)&outp[(m0 + r0 + j) * H_SZ + c0] = o;
        }
    }
}

// ---------------------------------------------------------------------------
// Kernel 2: causal flash attention, BQ=32, BK=64, 256 threads.
// grid (64, 4) -> 256 blocks, 48KB smem -> 2 blocks/SM, all co-resident.
// Thread layout 16x16: thread owns 2 q-rows x 4 kv-cols (GEMM1) and
// 2 q-rows x 4 h-cols (GEMM2). All smem traffic is LDS.128.
// K^T tile uses XOR column-block swizzle (cb ^= h>>2): conflict-free loads.
// ---------------------------------------------------------------------------
__global__ __launch_bounds__(256, 2) void attn_kernel(float* __restrict__ out)
{
    __shared__ __align__(16) float Qs[32 * 64];   // [r][h]
    __shared__ __align__(16) float Kt[64 * 64];   // [h][c-swizzled]
    __shared__ __align__(16) float Vs[64 * 64];   // [s][h]
    __shared__ __align__(16) float Ps[32 * 64];   // [r][s]

    const int tid = threadIdx.x;
    const int b   = blockIdx.y;
    const int qt  = 63 - blockIdx.x;       // longest blocks first
    const int q_base = qt * 32;

    const float* qb = g_q + b * T_SEQ * H_SZ;
    const float* kb = g_k + b * T_SEQ * H_SZ;
    const float* vb = g_v + b * T_SEQ * H_SZ;

    const int tx = tid & 15;
    const int ty = tid >> 4;
    const int r0 = ty * 2;
    const int c0 = tx * 4;

    // Load Q tile: 32 x 64 = 512 float4, 2 per thread.
    #pragma unroll
    for (int p = 0; p < 2; p++) {
        const int idx = tid + p * 256;
        const int r   = idx >> 4;
        const int h4  = idx & 15;
        *(float4*)&Qs[r * 64 + h4 * 4] =
            *(const float4*)&qb[(q_base + r) * H_SZ + h4 * 4];
    }

    float m_old[2], l[2], o[2][4];
    #pragma unroll
    for (int j = 0; j < 2; j++) {
        m_old[j] = -1e30f;
        l[j] = 0.0f;
        #pragma unroll
        for (int i = 0; i < 4; i++) o[j][i] = 0.0f;
    }
    __syncthreads();

    const int ntile = (qt >> 1) + 1;      // BK=64 tiles covering [0, q_end)
    for (int t = 0; t < ntile; t++) {
        const int k_base = t * 64;
        __syncthreads();   // previous GEMM2 done before overwriting Kt/Vs

        // Load K (transposed+swizzled) and V: 64x64 each.
        #pragma unroll
        for (int p = 0; p < 4; p++) {
            const int idx = tid + p * 256;
            const int c   = idx >> 4;      // 0..63
            const int h4  = idx & 15;      // 0..15
            float4 kv4 = *(const float4*)&kb[(k_base + c) * H_SZ + h4 * 4];
            const int pb = ((c >> 2) ^ h4) << 2;   // swizzled col block
            const int cl = c & 3;
            Kt[(h4 * 4 + 0) * 64 + pb + cl] = kv4.x;
            Kt[(h4 * 4 + 1) * 64 + pb + cl] = kv4.y;
            Kt[(h4 * 4 + 2) * 64 + pb + cl] = kv4.z;
            Kt[(h4 * 4 + 3) * 64 + pb + cl] = kv4.w;
            *(float4*)&Vs[c * 64 + h4 * 4] =
                *(const float4*)&vb[(k_base + c) * H_SZ + h4 * 4];
        }
        __syncthreads();

        // GEMM1: S = Q K^T, 2x4 per thread.
        float s[2][4];
        #pragma unroll
        for (int j = 0; j < 2; j++)
            #pragma unroll
            for (int i = 0; i < 4; i++) s[j][i] = 0.0f;

        #pragma unroll
        for (int h = 0; h < 64; h += 4) {
            const int sc = ((tx ^ (h >> 2)) << 2);   // swizzled column
            float4 k0 = *(const float4*)&Kt[(h + 0) * 64 + sc];
            float4 k1 = *(const float4*)&Kt[(h + 1) * 64 + sc];
            float4 k2 = *(const float4*)&Kt[(h + 2) * 64 + sc];
            float4 k3 = *(const float4*)&Kt[(h + 3) * 64 + sc];
            float4 q0 = *(const float4*)&Qs[(r0 + 0) * 64 + h];
            float4 q1 = *(const float4*)&Qs[(r0 + 1) * 64 + h];
            s[0][0] += q0.x*k0.x + q0.y*k1.x + q0.z*k2.x + q0.w*k3.x;
            s[0][1] += q0.x*k0.y + q0.y*k1.y + q0.z*k2.y + q0.w*k3.y;
            s[0][2] += q0.x*k0.z + q0.y*k1.z + q0.z*k2.z + q0.w*k3.z;
            s[0][3] += q0.x*k0.w + q0.y*k1.w + q0.z*k2.w + q0.w*k3.w;
            s[1][0] += q1.x*k0.x + q1.y*k1.x + q1.z*k2.x + q1.w*k3.x;
            s[1][1] += q1.x*k0.y + q1.y*k1.y + q1.z*k2.y + q1.w*k3.y;
            s[1][2] += q1.x*k0.z + q1.y*k1.z + q1.z*k2.z + q1.w*k3.z;
            s[1][3] += q1.x*k0.w + q1.y*k1.w + q1.z*k2.w + q1.w*k3.w;
        }

        // Scale + causal mask (last tile only needs the mask).
        const float scale = 0.125f;
        if (t == ntile - 1) {
            #pragma unroll
            for (int j = 0; j < 2; j++)
                #pragma unroll
                for (int i = 0; i < 4; i++) {
                    const int qg = q_base + r0 + j;
                    const int kg = k_base + c0 + i;
                    s[j][i] = (kg <= qg) ? s[j][i] * scale : -1e30f;
                }
        } else {
            #pragma unroll
            for (int j = 0; j < 2; j++)
                #pragma unroll
                for (int i = 0; i < 4; i++) s[j][i] *= scale;
        }

        // Row max over the 16 lanes sharing a row.
        float mt[2];
        #pragma unroll
        for (int j = 0; j < 2; j++)
            mt[j] = fmaxf(fmaxf(s[j][0], s[j][1]), fmaxf(s[j][2], s[j][3]));
        #pragma unroll
        for (int off = 1; off < 16; off <<= 1)
            #pragma unroll
            for (int j = 0; j < 2; j++)
                mt[j] = fmaxf(mt[j], __shfl_xor_sync(0xffffffffu, mt[j], off));

        float alpha[2], psum[2];
        #pragma unroll
        for (int j = 0; j < 2; j++) {
            const float mnew = fmaxf(m_old[j], mt[j]);
            alpha[j] = __expf(m_old[j] - mnew);
            m_old[j] = mnew;
            psum[j] = 0.0f;
            #pragma unroll
            for (int i = 0; i < 4; i++) {
                s[j][i] = __expf(s[j][i] - mnew);
                psum[j] += s[j][i];
            }
        }
        #pragma unroll
        for (int off = 1; off < 16; off <<= 1)
            #pragma unroll
            for (int j = 0; j < 2; j++)
                psum[j] += __shfl_xor_sync(0xffffffffu, psum[j], off);
        #pragma unroll
        for (int j = 0; j < 2; j++) {
            l[j] = l[j] * alpha[j] + psum[j];
            #pragma unroll
            for (int i = 0; i < 4; i++) o[j][i] *= alpha[j];
        }

        // Store P (natural layout, float4).
        #pragma unroll
        for (int j = 0; j < 2; j++) {
            float4 pv;
            pv.x = s[j][0]; pv.y = s[j][1]; pv.z = s[j][2]; pv.w = s[j][3];
            *(float4*)&Ps[(r0 + j) * 64 + c0] = pv;
        }
        __syncthreads();

        // GEMM2: O += P V, 2x4 per thread.
        #pragma unroll
        for (int ss = 0; ss < 64; ss += 4) {
            float4 p0 = *(const float4*)&Ps[(r0 + 0) * 64 + ss];
            float4 p1 = *(const float4*)&Ps[(r0 + 1) * 64 + ss];
            float4 v0 = *(const float4*)&Vs[(ss + 0) * 64 + c0];
            float4 v1 = *(const float4*)&Vs[(ss + 1) * 64 + c0];
            float4 v2 = *(const float4*)&Vs[(ss + 2) * 64 + c0];
            float4 v3 = *(const float4*)&Vs[(ss + 3) * 64 + c0];
            o[0][0] += p0.x*v0.x + p0.y*v1.x + p0.z*v2.x + p0.w*v3.x;
            o[0][1] += p0.x*v0.y + p0.y*v1.y + p0.z*v2.y + p0.w*v3.y;
            o[0][2] += p0.x*v0.z + p0.y*v1.z + p0.z*v2.z + p0.w*v3.z;
            o[0][3] += p0.x*v0.w + p0.y*v1.w + p0.z*v2.w + p0.w*v3.w;
            o[1][0] += p1.x*v0.x + p1.y*v1.x + p1.z*v2.x + p1.w*v3.x;
            o[1][1] += p1.x*v0.y + p1.y*v1.y + p1.z*v2.y + p1.w*v3.y;
            o[1][2] += p1.x*v0.z + p1.y*v1.z + p1.z*v2.z + p1.w*v3.z;
            o[1][3] += p1.x*v0.w + p1.y*v1.w + p1.z*v2.w + p1.w*v3.w;
        }
    }

    // Epilogue: normalize and store.
    float* ob = out + b * T_SEQ * H_SZ;
    #pragma unroll
    for (int j = 0; j < 2; j++) {
        const float inv_l = 1.0f / l[j];
        float4 t;
        t.x = o[j][0] * inv_l;
        t.y = o[j][1] * inv_l;
        t.z = o[j][2] * inv_l;
        t.w = o[j][3] * inv_l;
        *(float4*)&ob[(q_base + r0 + j) * H_SZ + c0] = t;
    }
}

extern "C" void kernel_launch(void* const* d_in, const int* in_sizes, int n_in,
                              void* d_out, int out_size)
{
    const float* x  = (const float*)d_in[0];
    const float* Wq = (const float*)d_in[1];
    const float* Wk = (const float*)d_in[2];
    const float* Wv = (const float*)d_in[3];
    float* out = (float*)d_out;

    qkv_kernel<<<M_TOT / 64, 256>>>(x, Wq, Wk, Wv);
    attn_kernel<<<dim3(64, B_SZ), 256>>>(out);
}

// round 5
// speedup vs baseline: 2.1498x; 1.9874x over previous
#include <cuda_runtime.h>
#include <cuda_bf16.h>
#include <cstdint>

#define D_IN 1024
#define H_SZ 64
#define M_TOT 8192   // B*T
#define T_SEQ 2048
#define B_SZ 4

// ---------------- global scratch ----------------
__device__ __nv_bfloat16 g_xh[M_TOT * D_IN];
__device__ __nv_bfloat16 g_xl[M_TOT * D_IN];
__device__ __nv_bfloat16 g_wh[192 * D_IN];     // [w*64+n][k]  (W transposed)
__device__ __nv_bfloat16 g_wl[192 * D_IN];
__device__ __nv_bfloat16 g_qh[M_TOT * H_SZ];   // [global token][h]
__device__ __nv_bfloat16 g_ql[M_TOT * H_SZ];
__device__ __nv_bfloat16 g_kh[M_TOT * H_SZ];
__device__ __nv_bfloat16 g_kl[M_TOT * H_SZ];
__device__ __nv_bfloat16 g_vth[B_SZ][H_SZ][T_SEQ];  // V transposed per batch
__device__ __nv_bfloat16 g_vtl[B_SZ][H_SZ][T_SEQ];

// ---------------- helpers ----------------
__device__ __forceinline__ void mma_bf16(float d[4], const uint32_t a[4],
                                         const uint32_t b[2]) {
    asm("mma.sync.aligned.m16n8k16.row.col.f32.bf16.bf16.f32 "
        "{%0,%1,%2,%3}, {%4,%5,%6,%7}, {%8,%9}, {%0,%1,%2,%3};\n"
        : "+f"(d[0]), "+f"(d[1]), "+f"(d[2]), "+f"(d[3])
        : "r"(a[0]), "r"(a[1]), "r"(a[2]), "r"(a[3]), "r"(b[0]), "r"(b[1]));
}

__device__ __forceinline__ uint32_t pack2bf(float v0, float v1) {
    unsigned short l = __bfloat16_as_ushort(__float2bfloat16(v0));
    unsigned short h = __bfloat16_as_ushort(__float2bfloat16(v1));
    return (uint32_t)l | ((uint32_t)h << 16);
}

// degree-6 Taylor of 2^x (rel err ~2e-5), FMA pipe only, no MUFU.
__device__ __forceinline__ float exp2_poly(float x) {
    x = fmaxf(x, -126.0f);
    float fl = floorf(x);
    float f  = x - fl;
    float p = 1.5403530e-4f;
    p = fmaf(p, f, 1.3333558e-3f);
    p = fmaf(p, f, 9.6181291e-3f);
    p = fmaf(p, f, 5.5504109e-2f);
    p = fmaf(p, f, 2.4022651e-1f);
    p = fmaf(p, f, 6.9314718e-1f);
    p = fmaf(p, f, 1.0f);
    int e = (int)fl;
    return __int_as_float((e + 127) << 23) * p;
}

// ---------------------------------------------------------------------------
// split x (fp32) -> bf16 hi + lo
// ---------------------------------------------------------------------------
__global__ __launch_bounds__(256) void split_x_kernel(const float* __restrict__ x)
{
    const int i = (blockIdx.x * 256 + threadIdx.x) * 4;
    float4 v = *(const float4*)&x[i];
    float vv[4] = {v.x, v.y, v.z, v.w};
    unsigned short hh[4], ll[4];
    #pragma unroll
    for (int j = 0; j < 4; j++) {
        __nv_bfloat16 h = __float2bfloat16(vv[j]);
        hh[j] = __bfloat16_as_ushort(h);
        ll[j] = __bfloat16_as_ushort(__float2bfloat16(vv[j] - __bfloat162float(h)));
    }
    *(uint2*)&g_xh[i] = make_uint2((uint32_t)hh[0] | ((uint32_t)hh[1] << 16),
                                   (uint32_t)hh[2] | ((uint32_t)hh[3] << 16));
    *(uint2*)&g_xl[i] = make_uint2((uint32_t)ll[0] | ((uint32_t)ll[1] << 16),
                                   (uint32_t)ll[2] | ((uint32_t)ll[3] << 16));
}

// ---------------------------------------------------------------------------
// transpose + split W: [k][n] fp32 -> [w*64+n][k] bf16 hi/lo
// ---------------------------------------------------------------------------
__global__ __launch_bounds__(256) void split_w_kernel(
    const float* __restrict__ Wq, const float* __restrict__ Wk,
    const float* __restrict__ Wv)
{
    const int idx = blockIdx.x * 256 + threadIdx.x;
    const int w = idx >> 16;
    const int n = (idx >> 10) & 63;
    const int k = idx & 1023;
    const float* W = (w == 0) ? Wq : ((w == 1) ? Wk : Wv);
    const float val = W[k * 64 + n];
    __nv_bfloat16 h = __float2bfloat16(val);
    g_wh[idx] = h;
    g_wl[idx] = __float2bfloat16(val - __bfloat162float(h));
}

// ---------------------------------------------------------------------------
// QKV projection via mma.sync bf16 (3-term split). 128 threads, tile M=64,
// N=192 (q|k|v), K chunks of 32. Warp grid 2m x 2n.
// Epilogue: q,k -> [token][h] hi/lo; v -> transposed [b][h][t] hi/lo.
// ---------------------------------------------------------------------------
__global__ __launch_bounds__(128, 1) void qkv_mma_kernel()
{
    __shared__ __align__(16) __nv_bfloat16 xs_h[64][40], xs_l[64][40];
    __shared__ __align__(16) __nv_bfloat16 ws_h[192][40], ws_l[192][40];

    const int tid  = threadIdx.x;
    const int lane = tid & 31;
    const int wid  = tid >> 5;
    const int wm = wid & 1, wn = wid >> 1;
    const int lq = lane >> 2;
    const int lc = (lane & 3) * 2;
    const int m0 = blockIdx.x * 64;

    float d[2][12][4];
    #pragma unroll
    for (int mf = 0; mf < 2; mf++)
        #pragma unroll
        for (int j = 0; j < 12; j++)
            #pragma unroll
            for (int r = 0; r < 4; r++) d[mf][j][r] = 0.0f;

    for (int c = 0; c < 32; c++) {
        const int k0 = c * 32;
        __syncthreads();
        #pragma unroll
        for (int p = 0; p < 2; p++) {
            const int idx = tid + p * 128;
            const int r = idx >> 2, u = idx & 3;
            *(uint4*)&xs_h[r][u * 8] = *(const uint4*)&g_xh[(m0 + r) * D_IN + k0 + u * 8];
            *(uint4*)&xs_l[r][u * 8] = *(const uint4*)&g_xl[(m0 + r) * D_IN + k0 + u * 8];
        }
        #pragma unroll
        for (int p = 0; p < 6; p++) {
            const int idx = tid + p * 128;
            const int r = idx >> 2, u = idx & 3;
            *(uint4*)&ws_h[r][u * 8] = *(const uint4*)&g_wh[r * D_IN + k0 + u * 8];
            *(uint4*)&ws_l[r][u * 8] = *(const uint4*)&g_wl[r * D_IN + k0 + u * 8];
        }
        __syncthreads();

        #pragma unroll
        for (int kc = 0; kc < 2; kc++) {
            uint32_t ah[2][4], al[2][4];
            const int cb = kc * 16 + lc;
            #pragma unroll
            for (int mf = 0; mf < 2; mf++) {
                const int rb = wm * 32 + mf * 16;
                ah[mf][0] = *(const uint32_t*)&xs_h[rb + lq][cb];
                ah[mf][1] = *(const uint32_t*)&xs_h[rb + lq + 8][cb];
                ah[mf][2] = *(const uint32_t*)&xs_h[rb + lq][cb + 8];
                ah[mf][3] = *(const uint32_t*)&xs_h[rb + lq + 8][cb + 8];
                al[mf][0] = *(const uint32_t*)&xs_l[rb + lq][cb];
                al[mf][1] = *(const uint32_t*)&xs_l[rb + lq + 8][cb];
                al[mf][2] = *(const uint32_t*)&xs_l[rb + lq][cb + 8];
                al[mf][3] = *(const uint32_t*)&xs_l[rb + lq + 8][cb + 8];
            }
            #pragma unroll
            for (int j = 0; j < 12; j++) {
                const int wr = wn * 96 + j * 8 + lq;
                uint32_t bh[2], bl[2];
                bh[0] = *(const uint32_t*)&ws_h[wr][cb];
                bh[1] = *(const uint32_t*)&ws_h[wr][cb + 8];
                bl[0] = *(const uint32_t*)&ws_l[wr][cb];
                bl[1] = *(const uint32_t*)&ws_l[wr][cb + 8];
                #pragma unroll
                for (int mf = 0; mf < 2; mf++) {
                    mma_bf16(d[mf][j], ah[mf], bh);
                    mma_bf16(d[mf][j], ah[mf], bl);
                    mma_bf16(d[mf][j], al[mf], bh);
                }
            }
        }
    }

    // epilogue: hi/lo split + store
    #pragma unroll
    for (int mf = 0; mf < 2; mf++) {
        #pragma unroll
        for (int j = 0; j < 12; j++) {
            const int col = wn * 96 + j * 8 + lc;
            const int mat = col >> 6;
            const int h   = col & 63;
            #pragma unroll
            for (int half = 0; half < 2; half++) {
                const int row = m0 + wm * 32 + mf * 16 + lq + half * 8;
                const float v0 = d[mf][j][half * 2 + 0];
                const float v1 = d[mf][j][half * 2 + 1];
                __nv_bfloat16 h0 = __float2bfloat16(v0);
                __nv_bfloat16 h1 = __float2bfloat16(v1);
                float l0 = v0 - __bfloat162float(h0);
                float l1 = v1 - __bfloat162float(h1);
                if (mat == 0) {
                    *(uint32_t*)&g_qh[row * 64 + h] =
                        (uint32_t)__bfloat16_as_ushort(h0) |
                        ((uint32_t)__bfloat16_as_ushort(h1) << 16);
                    *(uint32_t*)&g_ql[row * 64 + h] = pack2bf(l0, l1);
                } else if (mat == 1) {
                    *(uint32_t*)&g_kh[row * 64 + h] =
                        (uint32_t)__bfloat16_as_ushort(h0) |
                        ((uint32_t)__bfloat16_as_ushort(h1) << 16);
                    *(uint32_t*)&g_kl[row * 64 + h] = pack2bf(l0, l1);
                } else {
                    const int b = row >> 11, t = row & 2047;
                    g_vth[b][h][t]     = h0;
                    g_vth[b][h + 1][t] = h1;
                    g_vtl[b][h][t]     = __float2bfloat16(l0);
                    g_vtl[b][h + 1][t] = __float2bfloat16(l1);
                }
            }
        }
    }
}

// ---------------------------------------------------------------------------
// Flash attention via mma.sync bf16. BQ=32, BK=64, 128 threads (4 warps 2m x 2n).
// P tiles alias the K tiles (safe: separated by syncs). Poly exp2, no MUFU.
// ---------------------------------------------------------------------------
#define SCALE_L2E 0.18033688f   // 64^-0.5 * log2(e)

__global__ __launch_bounds__(128, 3) void attn_kernel(float* __restrict__ out)
{
    __shared__ __align__(16) char smbuf[46592];
    __nv_bfloat16* Qh = (__nv_bfloat16*)(smbuf + 0);      // [32][72]
    __nv_bfloat16* Ql = (__nv_bfloat16*)(smbuf + 4608);
    __nv_bfloat16* Kh = (__nv_bfloat16*)(smbuf + 9216);   // [64][72]
    __nv_bfloat16* Kl = (__nv_bfloat16*)(smbuf + 18432);
    __nv_bfloat16* Vh = (__nv_bfloat16*)(smbuf + 27648);  // [64][72] (Vt: [h][s])
    __nv_bfloat16* Vl = (__nv_bfloat16*)(smbuf + 36864);
    __nv_bfloat16* Ph = Kh;                               // alias (post-GEMM1)
    __nv_bfloat16* Pl = Kl;
    float* red_max = (float*)(smbuf + 46080);             // [2][32]
    float* red_sum = red_max + 64;                        // [2][32]

    const int tid  = threadIdx.x;
    const int lane = tid & 31;
    const int wid  = tid >> 5;
    const int wm = wid & 1, wn = wid >> 1;
    const int lq = lane >> 2;
    const int lc = (lane & 3) * 2;

    const int b  = blockIdx.y;
    const int qt = 63 - blockIdx.x;     // longest-first
    const int q_base = qt * 32;

    // *** R5 FIX: batch offset for Q/K token rows ***
    const int boff = b * T_SEQ * 64;
    const __nv_bfloat16* qbh = g_qh + boff;
    const __nv_bfloat16* qbl = g_ql + boff;
    const __nv_bfloat16* kbh = g_kh + boff;
    const __nv_bfloat16* kbl = g_kl + boff;

    // load Q tile (hi/lo): 32 rows x 64 h
    #pragma unroll
    for (int p = 0; p < 2; p++) {
        const int idx = tid + p * 128;
        const int r = idx >> 3, u = idx & 7;
        *(uint4*)&Qh[r * 72 + u * 8] =
            *(const uint4*)&qbh[(q_base + r) * 64 + u * 8];
        *(uint4*)&Ql[r * 72 + u * 8] =
            *(const uint4*)&qbl[(q_base + r) * 64 + u * 8];
    }
    __syncthreads();

    // preload Q fragments (loop-invariant)
    uint32_t qa_h[4][4], qa_l[4][4];
    {
        const int rb = wm * 16;
        #pragma unroll
        for (int kc = 0; kc < 4; kc++) {
            const int cb = kc * 16 + lc;
            qa_h[kc][0] = *(const uint32_t*)&Qh[(rb + lq) * 72 + cb];
            qa_h[kc][1] = *(const uint32_t*)&Qh[(rb + lq + 8) * 72 + cb];
            qa_h[kc][2] = *(const uint32_t*)&Qh[(rb + lq) * 72 + cb + 8];
            qa_h[kc][3] = *(const uint32_t*)&Qh[(rb + lq + 8) * 72 + cb + 8];
            qa_l[kc][0] = *(const uint32_t*)&Ql[(rb + lq) * 72 + cb];
            qa_l[kc][1] = *(const uint32_t*)&Ql[(rb + lq + 8) * 72 + cb];
            qa_l[kc][2] = *(const uint32_t*)&Ql[(rb + lq) * 72 + cb + 8];
            qa_l[kc][3] = *(const uint32_t*)&Ql[(rb + lq + 8) * 72 + cb + 8];
        }
    }

    float of[4][4];
    #pragma unroll
    for (int j = 0; j < 4; j++)
        #pragma unroll
        for (int r = 0; r < 4; r++) of[j][r] = 0.0f;
    float m2[2] = {-1e30f, -1e30f};
    float lsum[2] = {0.0f, 0.0f};

    const int ntile = (qt >> 1) + 1;
    for (int t = 0; t < ntile; t++) {
        const int kb = t * 64;
        __syncthreads();   // prior GEMM2 done (Vh/Kh reuse)
        #pragma unroll
        for (int p = 0; p < 4; p++) {
            const int idx = tid + p * 128;
            const int r = idx >> 3, u = idx & 7;
            *(uint4*)&Kh[r * 72 + u * 8] =
                *(const uint4*)&kbh[(kb + r) * 64 + u * 8];
            *(uint4*)&Kl[r * 72 + u * 8] =
                *(const uint4*)&kbl[(kb + r) * 64 + u * 8];
            *(uint4*)&Vh[r * 72 + u * 8] =
                *(const uint4*)&g_vth[b][r][kb + u * 8];
            *(uint4*)&Vl[r * 72 + u * 8] =
                *(const uint4*)&g_vtl[b][r][kb + u * 8];
        }
        __syncthreads();

        // GEMM1: S = Q K^T (3-term split)
        float s[4][4];
        #pragma unroll
        for (int j = 0; j < 4; j++)
            #pragma unroll
            for (int r = 0; r < 4; r++) s[j][r] = 0.0f;
        #pragma unroll
        for (int kc = 0; kc < 4; kc++) {
            const int cb = kc * 16 + lc;
            #pragma unroll
            for (int j = 0; j < 4; j++) {
                const int sr = wn * 32 + j * 8 + lq;
                uint32_t bh[2], bl[2];
                bh[0] = *(const uint32_t*)&Kh[sr * 72 + cb];
                bh[1] = *(const uint32_t*)&Kh[sr * 72 + cb + 8];
                bl[0] = *(const uint32_t*)&Kl[sr * 72 + cb];
                bl[1] = *(const uint32_t*)&Kl[sr * 72 + cb + 8];
                mma_bf16(s[j], qa_h[kc], bh);
                mma_bf16(s[j], qa_h[kc], bl);
                mma_bf16(s[j], qa_l[kc], bh);
            }
        }

        // scale into log2 domain + causal mask (last tile only)
        if (t == ntile - 1) {
            #pragma unroll
            for (int j = 0; j < 4; j++) {
                const int col = kb + wn * 32 + j * 8 + lc;
                #pragma unroll
                for (int half = 0; half < 2; half++) {
                    const int qrow = q_base + wm * 16 + lq + half * 8;
                    s[j][half * 2 + 0] = (col     <= qrow) ? s[j][half * 2 + 0] * SCALE_L2E : -1e30f;
                    s[j][half * 2 + 1] = (col + 1 <= qrow) ? s[j][half * 2 + 1] * SCALE_L2E : -1e30f;
                }
            }
        } else {
            #pragma unroll
            for (int j = 0; j < 4; j++)
                #pragma unroll
                for (int r = 0; r < 4; r++) s[j][r] *= SCALE_L2E;
        }

        // partial row max (this warp's 32 cols)
        float pm[2] = {-1e30f, -1e30f};
        #pragma unroll
        for (int j = 0; j < 4; j++) {
            pm[0] = fmaxf(pm[0], fmaxf(s[j][0], s[j][1]));
            pm[1] = fmaxf(pm[1], fmaxf(s[j][2], s[j][3]));
        }
        #pragma unroll
        for (int off = 1; off < 4; off <<= 1) {
            pm[0] = fmaxf(pm[0], __shfl_xor_sync(0xffffffffu, pm[0], off));
            pm[1] = fmaxf(pm[1], __shfl_xor_sync(0xffffffffu, pm[1], off));
        }
        if ((lane & 3) == 0) {
            red_max[wn * 32 + wm * 16 + lq]     = pm[0];
            red_max[wn * 32 + wm * 16 + lq + 8] = pm[1];
        }
        __syncthreads();

        // combined max + exp + partial sum + P store
        float mnew[2], alpha[2];
        #pragma unroll
        for (int half = 0; half < 2; half++) {
            const int r = wm * 16 + lq + half * 8;
            const float cm = fmaxf(red_max[r], red_max[32 + r]);
            mnew[half]  = fmaxf(m2[half], cm);
            alpha[half] = exp2_poly(m2[half] - mnew[half]);
            m2[half]    = mnew[half];
        }
        float ps[2] = {0.0f, 0.0f};
        #pragma unroll
        for (int j = 0; j < 4; j++) {
            #pragma unroll
            for (int half = 0; half < 2; half++) {
                float p0 = exp2_poly(s[j][half * 2 + 0] - mnew[half]);
                float p1 = exp2_poly(s[j][half * 2 + 1] - mnew[half]);
                ps[half] += p0 + p1;
                __nv_bfloat16 h0 = __float2bfloat16(p0);
                __nv_bfloat16 h1 = __float2bfloat16(p1);
                const int prow = wm * 16 + lq + half * 8;
                const int pcol = wn * 32 + j * 8 + lc;
                *(uint32_t*)&Ph[prow * 72 + pcol] =
                    (uint32_t)__bfloat16_as_ushort(h0) |
                    ((uint32_t)__bfloat16_as_ushort(h1) << 16);
                *(uint32_t*)&Pl[prow * 72 + pcol] =
                    pack2bf(p0 - __bfloat162float(h0), p1 - __bfloat162float(h1));
            }
        }
        #pragma unroll
        for (int off = 1; off < 4; off <<= 1) {
            ps[0] += __shfl_xor_sync(0xffffffffu, ps[0], off);
            ps[1] += __shfl_xor_sync(0xffffffffu, ps[1], off);
        }
        if ((lane & 3) == 0) {
            red_sum[wn * 32 + wm * 16 + lq]     = ps[0];
            red_sum[wn * 32 + wm * 16 + lq + 8] = ps[1];
        }
        __syncthreads();

        #pragma unroll
        for (int half = 0; half < 2; half++) {
            const int r = wm * 16 + lq + half * 8;
            lsum[half] = lsum[half] * alpha[half] + red_sum[r] + red_sum[32 + r];
        }
        #pragma unroll
        for (int j = 0; j < 4; j++) {
            of[j][0] *= alpha[0]; of[j][1] *= alpha[0];
            of[j][2] *= alpha[1]; of[j][3] *= alpha[1];
        }

        // GEMM2: O += P V (3-term split), V is [h][s] so B frag is direct
        #pragma unroll
        for (int kc = 0; kc < 4; kc++) {
            const int cb = kc * 16 + lc;
            uint32_t ap_h[4], ap_l[4];
            const int rb = wm * 16;
            ap_h[0] = *(const uint32_t*)&Ph[(rb + lq) * 72 + cb];
            ap_h[1] = *(const uint32_t*)&Ph[(rb + lq + 8) * 72 + cb];
            ap_h[2] = *(const uint32_t*)&Ph[(rb + lq) * 72 + cb + 8];
            ap_h[3] = *(const uint32_t*)&Ph[(rb + lq + 8) * 72 + cb + 8];
            ap_l[0] = *(const uint32_t*)&Pl[(rb + lq) * 72 + cb];
            ap_l[1] = *(const uint32_t*)&Pl[(rb + lq + 8) * 72 + cb];
            ap_l[2] = *(const uint32_t*)&Pl[(rb + lq) * 72 + cb + 8];
            ap_l[3] = *(const uint32_t*)&Pl[(rb + lq + 8) * 72 + cb + 8];
            #pragma unroll
            for (int j = 0; j < 4; j++) {
                const int hr = wn * 32 + j * 8 + lq;
                uint32_t bh[2], bl[2];
                bh[0] = *(const uint32_t*)&Vh[hr * 72 + cb];
                bh[1] = *(const uint32_t*)&Vh[hr * 72 + cb + 8];
                bl[0] = *(const uint32_t*)&Vl[hr * 72 + cb];
                bl[1] = *(const uint32_t*)&Vl[hr * 72 + cb + 8];
                mma_bf16(of[j], ap_h, bh);
                mma_bf16(of[j], ap_h, bl);
                mma_bf16(of[j], ap_l, bh);
            }
        }
    }

    // epilogue
    const float inv0 = 1.0f / lsum[0];
    const float inv1 = 1.0f / lsum[1];
    float* ob = out + b * T_SEQ * H_SZ;
    #pragma unroll
    for (int j = 0; j < 4; j++) {
        const int col = wn * 32 + j * 8 + lc;
        const int row0 = q_base + wm * 16 + lq;
        float2 o0 = make_float2(of[j][0] * inv0, of[j][1] * inv0);
        float2 o1 = make_float2(of[j][2] * inv1, of[j][3] * inv1);
        *(float2*)&ob[row0 * 64 + col]       = o0;
        *(float2*)&ob[(row0 + 8) * 64 + col] = o1;
    }
}

extern "C" void kernel_launch(void* const* d_in, const int* in_sizes, int n_in,
                              void* d_out, int out_size)
{
    const float* x  = (const float*)d_in[0];
    const float* Wq = (const float*)d_in[1];
    const float* Wk = (const float*)d_in[2];
    const float* Wv = (const float*)d_in[3];
    float* out = (float*)d_out;

    split_x_kernel<<<M_TOT * D_IN / 1024, 256>>>(x);
    split_w_kernel<<<3 * 64 * 1024 / 256, 256>>>(Wq, Wk, Wv);
    qkv_mma_kernel<<<M_TOT / 64, 128>>>();
    attn_kernel<<<dim3(64, B_SZ), 128>>>(out);
}

// round 6
// speedup vs baseline: 2.2984x; 1.0692x over previous
#include <cuda_runtime.h>
#include <cuda_bf16.h>
#include <cstdint>

#define D_IN 1024
#define H_SZ 64
#define M_TOT 8192   // B*T
#define T_SEQ 2048
#define B_SZ 4
#define NSPLIT 4
#define TILES_PER_SPLIT 8

// ---------------- global scratch ----------------
__device__ __nv_bfloat16 g_xh[M_TOT * D_IN];
__device__ __nv_bfloat16 g_xl[M_TOT * D_IN];
__device__ __nv_bfloat16 g_wh[192 * D_IN];     // [w*64+n][k]  (W transposed)
__device__ __nv_bfloat16 g_wl[192 * D_IN];
__device__ __nv_bfloat16 g_qh[M_TOT * H_SZ];   // [global token][h]
__device__ __nv_bfloat16 g_ql[M_TOT * H_SZ];
__device__ __nv_bfloat16 g_kh[M_TOT * H_SZ];
__device__ __nv_bfloat16 g_kl[M_TOT * H_SZ];
__device__ __nv_bfloat16 g_vth[B_SZ][H_SZ][T_SEQ];  // V transposed per batch
__device__ __nv_bfloat16 g_vtl[B_SZ][H_SZ][T_SEQ];
// split-KV partials
__device__ float g_po[NSPLIT][M_TOT][H_SZ];    // unnormalized O
__device__ float g_pm[NSPLIT][M_TOT];          // running max (log2 domain)
__device__ float g_pl[NSPLIT][M_TOT];          // running sum

// ---------------- helpers ----------------
__device__ __forceinline__ void mma_bf16(float d[4], const uint32_t a[4],
                                         const uint32_t b[2]) {
    asm("mma.sync.aligned.m16n8k16.row.col.f32.bf16.bf16.f32 "
        "{%0,%1,%2,%3}, {%4,%5,%6,%7}, {%8,%9}, {%0,%1,%2,%3};\n"
        : "+f"(d[0]), "+f"(d[1]), "+f"(d[2]), "+f"(d[3])
        : "r"(a[0]), "r"(a[1]), "r"(a[2]), "r"(a[3]), "r"(b[0]), "r"(b[1]));
}

__device__ __forceinline__ uint32_t pack2bf(float v0, float v1) {
    unsigned short l = __bfloat16_as_ushort(__float2bfloat16(v0));
    unsigned short h = __bfloat16_as_ushort(__float2bfloat16(v1));
    return (uint32_t)l | ((uint32_t)h << 16);
}

// degree-6 Taylor of 2^x (rel err ~2e-5), FMA pipe only, no MUFU.
__device__ __forceinline__ float exp2_poly(float x) {
    x = fmaxf(x, -126.0f);
    float fl = floorf(x);
    float f  = x - fl;
    float p = 1.5403530e-4f;
    p = fmaf(p, f, 1.3333558e-3f);
    p = fmaf(p, f, 9.6181291e-3f);
    p = fmaf(p, f, 5.5504109e-2f);
    p = fmaf(p, f, 2.4022651e-1f);
    p = fmaf(p, f, 6.9314718e-1f);
    p = fmaf(p, f, 1.0f);
    int e = (int)fl;
    return __int_as_float((e + 127) << 23) * p;
}

// ---------------------------------------------------------------------------
// split x (fp32) -> bf16 hi + lo
// ---------------------------------------------------------------------------
__global__ __launch_bounds__(256) void split_x_kernel(const float* __restrict__ x)
{
    const int i = (blockIdx.x * 256 + threadIdx.x) * 4;
    float4 v = *(const float4*)&x[i];
    float vv[4] = {v.x, v.y, v.z, v.w};
    unsigned short hh[4], ll[4];
    #pragma unroll
    for (int j = 0; j < 4; j++) {
        __nv_bfloat16 h = __float2bfloat16(vv[j]);
        hh[j] = __bfloat16_as_ushort(h);
        ll[j] = __bfloat16_as_ushort(__float2bfloat16(vv[j] - __bfloat162float(h)));
    }
    *(uint2*)&g_xh[i] = make_uint2((uint32_t)hh[0] | ((uint32_t)hh[1] << 16),
                                   (uint32_t)hh[2] | ((uint32_t)hh[3] << 16));
    *(uint2*)&g_xl[i] = make_uint2((uint32_t)ll[0] | ((uint32_t)ll[1] << 16),
                                   (uint32_t)ll[2] | ((uint32_t)ll[3] << 16));
}

// ---------------------------------------------------------------------------
// transpose + split W: [k][n] fp32 -> [w*64+n][k] bf16 hi/lo
// ---------------------------------------------------------------------------
__global__ __launch_bounds__(256) void split_w_kernel(
    const float* __restrict__ Wq, const float* __restrict__ Wk,
    const float* __restrict__ Wv)
{
    const int idx = blockIdx.x * 256 + threadIdx.x;
    const int w = idx >> 16;
    const int n = (idx >> 10) & 63;
    const int k = idx & 1023;
    const float* W = (w == 0) ? Wq : ((w == 1) ? Wk : Wv);
    const float val = W[k * 64 + n];
    __nv_bfloat16 h = __float2bfloat16(val);
    g_wh[idx] = h;
    g_wl[idx] = __float2bfloat16(val - __bfloat162float(h));
}

// ---------------------------------------------------------------------------
// QKV projection via mma.sync bf16 (3-term split). 128 threads, tile M=32,
// N=192 (q|k|v), K chunks of 32. 256 CTAs. Warp grid 1m x 4n.
// ---------------------------------------------------------------------------
__global__ __launch_bounds__(128) void qkv_mma_kernel()
{
    __shared__ __align__(16) __nv_bfloat16 xs_h[32][40], xs_l[32][40];
    __shared__ __align__(16) __nv_bfloat16 ws_h[192][40], ws_l[192][40];

    const int tid  = threadIdx.x;
    const int lane = tid & 31;
    const int wn   = tid >> 5;         // warp = n-slice (48 cols each)
    const int lq = lane >> 2;
    const int lc = (lane & 3) * 2;
    const int m0 = blockIdx.x * 32;

    float d[2][6][4];
    #pragma unroll
    for (int mf = 0; mf < 2; mf++)
        #pragma unroll
        for (int j = 0; j < 6; j++)
            #pragma unroll
            for (int r = 0; r < 4; r++) d[mf][j][r] = 0.0f;

    for (int c = 0; c < 32; c++) {
        const int k0 = c * 32;
        __syncthreads();
        {   // x tile: 32 rows x 32 k = 128 uint4 per buffer, 1/thread
            const int r = tid >> 2, u = tid & 3;
            *(uint4*)&xs_h[r][u * 8] = *(const uint4*)&g_xh[(m0 + r) * D_IN + k0 + u * 8];
            *(uint4*)&xs_l[r][u * 8] = *(const uint4*)&g_xl[(m0 + r) * D_IN + k0 + u * 8];
        }
        #pragma unroll
        for (int p = 0; p < 6; p++) {   // w tiles: 192 x 32 = 768 uint4
            const int idx = tid + p * 128;
            const int r = idx >> 2, u = idx & 3;
            *(uint4*)&ws_h[r][u * 8] = *(const uint4*)&g_wh[r * D_IN + k0 + u * 8];
            *(uint4*)&ws_l[r][u * 8] = *(const uint4*)&g_wl[r * D_IN + k0 + u * 8];
        }
        __syncthreads();

        #pragma unroll
        for (int kc = 0; kc < 2; kc++) {
            uint32_t ah[2][4], al[2][4];
            const int cb = kc * 16 + lc;
            #pragma unroll
            for (int mf = 0; mf < 2; mf++) {
                const int rb = mf * 16;
                ah[mf][0] = *(const uint32_t*)&xs_h[rb + lq][cb];
                ah[mf][1] = *(const uint32_t*)&xs_h[rb + lq + 8][cb];
                ah[mf][2] = *(const uint32_t*)&xs_h[rb + lq][cb + 8];
                ah[mf][3] = *(const uint32_t*)&xs_h[rb + lq + 8][cb + 8];
                al[mf][0] = *(const uint32_t*)&xs_l[rb + lq][cb];
                al[mf][1] = *(const uint32_t*)&xs_l[rb + lq + 8][cb];
                al[mf][2] = *(const uint32_t*)&xs_l[rb + lq][cb + 8];
                al[mf][3] = *(const uint32_t*)&xs_l[rb + lq + 8][cb + 8];
            }
            #pragma unroll
            for (int j = 0; j < 6; j++) {
                const int wr = wn * 48 + j * 8 + lq;
                uint32_t bh[2], bl[2];
                bh[0] = *(const uint32_t*)&ws_h[wr][cb];
                bh[1] = *(const uint32_t*)&ws_h[wr][cb + 8];
                bl[0] = *(const uint32_t*)&ws_l[wr][cb];
                bl[1] = *(const uint32_t*)&ws_l[wr][cb + 8];
                #pragma unroll
                for (int mf = 0; mf < 2; mf++) {
                    mma_bf16(d[mf][j], ah[mf], bh);
                    mma_bf16(d[mf][j], ah[mf], bl);
                    mma_bf16(d[mf][j], al[mf], bh);
                }
            }
        }
    }

    // epilogue: hi/lo split + store
    #pragma unroll
    for (int mf = 0; mf < 2; mf++) {
        #pragma unroll
        for (int j = 0; j < 6; j++) {
            const int col = wn * 48 + j * 8 + lc;
            const int mat = col >> 6;
            const int h   = col & 63;
            #pragma unroll
            for (int half = 0; half < 2; half++) {
                const int row = m0 + mf * 16 + lq + half * 8;
                const float v0 = d[mf][j][half * 2 + 0];
                const float v1 = d[mf][j][half * 2 + 1];
                __nv_bfloat16 h0 = __float2bfloat16(v0);
                __nv_bfloat16 h1 = __float2bfloat16(v1);
                float l0 = v0 - __bfloat162float(h0);
                float l1 = v1 - __bfloat162float(h1);
                if (mat == 0) {
                    *(uint32_t*)&g_qh[row * 64 + h] =
                        (uint32_t)__bfloat16_as_ushort(h0) |
                        ((uint32_t)__bfloat16_as_ushort(h1) << 16);
                    *(uint32_t*)&g_ql[row * 64 + h] = pack2bf(l0, l1);
                } else if (mat == 1) {
                    *(uint32_t*)&g_kh[row * 64 + h] =
                        (uint32_t)__bfloat16_as_ushort(h0) |
                        ((uint32_t)__bfloat16_as_ushort(h1) << 16);
                    *(uint32_t*)&g_kl[row * 64 + h] = pack2bf(l0, l1);
                } else {
                    const int b = row >> 11, t = row & 2047;
                    g_vth[b][h][t]     = h0;
                    g_vth[b][h + 1][t] = h1;
                    g_vtl[b][h][t]     = __float2bfloat16(l0);
                    g_vtl[b][h + 1][t] = __float2bfloat16(l1);
                }
            }
        }
    }
}

// ---------------------------------------------------------------------------
// Split-KV flash attention. grid (64, B, NSPLIT), block 128 (4 warps 2m x 2n).
// Each block processes <= 8 kv tiles and writes partial (m, l, O_raw).
// ---------------------------------------------------------------------------
#define SCALE_L2E 0.18033688f   // 64^-0.5 * log2(e)

__global__ __launch_bounds__(128, 3) void attn_kernel()
{
    const int qt = 63 - blockIdx.x;     // longest-first
    const int ntile = (qt >> 1) + 1;
    const int sp = blockIdx.z;
    const int t0 = sp * TILES_PER_SPLIT;
    if (t0 >= ntile) return;
    const int t1 = min(t0 + TILES_PER_SPLIT, ntile);

    __shared__ __align__(16) char smbuf[46592];
    __nv_bfloat16* Qh = (__nv_bfloat16*)(smbuf + 0);      // [32][72]
    __nv_bfloat16* Ql = (__nv_bfloat16*)(smbuf + 4608);
    __nv_bfloat16* Kh = (__nv_bfloat16*)(smbuf + 9216);   // [64][72]
    __nv_bfloat16* Kl = (__nv_bfloat16*)(smbuf + 18432);
    __nv_bfloat16* Vh = (__nv_bfloat16*)(smbuf + 27648);  // [64][72] (Vt: [h][s])
    __nv_bfloat16* Vl = (__nv_bfloat16*)(smbuf + 36864);
    __nv_bfloat16* Ph = Kh;                               // alias (post-GEMM1)
    __nv_bfloat16* Pl = Kl;
    float* red_max = (float*)(smbuf + 46080);             // [2][32]
    float* red_sum = red_max + 64;                        // [2][32]

    const int tid  = threadIdx.x;
    const int lane = tid & 31;
    const int wid  = tid >> 5;
    const int wm = wid & 1, wn = wid >> 1;
    const int lq = lane >> 2;
    const int lc = (lane & 3) * 2;

    const int b  = blockIdx.y;
    const int q_base = qt * 32;

    const int boff = b * T_SEQ * 64;
    const __nv_bfloat16* qbh = g_qh + boff;
    const __nv_bfloat16* qbl = g_ql + boff;
    const __nv_bfloat16* kbh = g_kh + boff;
    const __nv_bfloat16* kbl = g_kl + boff;

    // load Q tile (hi/lo): 32 rows x 64 h
    #pragma unroll
    for (int p = 0; p < 2; p++) {
        const int idx = tid + p * 128;
        const int r = idx >> 3, u = idx & 7;
        *(uint4*)&Qh[r * 72 + u * 8] =
            *(const uint4*)&qbh[(q_base + r) * 64 + u * 8];
        *(uint4*)&Ql[r * 72 + u * 8] =
            *(const uint4*)&qbl[(q_base + r) * 64 + u * 8];
    }
    __syncthreads();

    // preload Q fragments (loop-invariant)
    uint32_t qa_h[4][4], qa_l[4][4];
    {
        const int rb = wm * 16;
        #pragma unroll
        for (int kc = 0; kc < 4; kc++) {
            const int cb = kc * 16 + lc;
            qa_h[kc][0] = *(const uint32_t*)&Qh[(rb + lq) * 72 + cb];
            qa_h[kc][1] = *(const uint32_t*)&Qh[(rb + lq + 8) * 72 + cb];
            qa_h[kc][2] = *(const uint32_t*)&Qh[(rb + lq) * 72 + cb + 8];
            qa_h[kc][3] = *(const uint32_t*)&Qh[(rb + lq + 8) * 72 + cb + 8];
            qa_l[kc][0] = *(const uint32_t*)&Ql[(rb + lq) * 72 + cb];
            qa_l[kc][1] = *(const uint32_t*)&Ql[(rb + lq + 8) * 72 + cb];
            qa_l[kc][2] = *(const uint32_t*)&Ql[(rb + lq) * 72 + cb + 8];
            qa_l[kc][3] = *(const uint32_t*)&Ql[(rb + lq + 8) * 72 + cb + 8];
        }
    }

    float of[4][4];
    #pragma unroll
    for (int j = 0; j < 4; j++)
        #pragma unroll
        for (int r = 0; r < 4; r++) of[j][r] = 0.0f;
    float m2[2] = {-1e30f, -1e30f};
    float lsum[2] = {0.0f, 0.0f};

    for (int t = t0; t < t1; t++) {
        const int kb = t * 64;
        __syncthreads();   // prior GEMM2 done (Vh/Kh reuse)
        #pragma unroll
        for (int p = 0; p < 4; p++) {
            const int idx = tid + p * 128;
            const int r = idx >> 3, u = idx & 7;
            *(uint4*)&Kh[r * 72 + u * 8] =
                *(const uint4*)&kbh[(kb + r) * 64 + u * 8];
            *(uint4*)&Kl[r * 72 + u * 8] =
                *(const uint4*)&kbl[(kb + r) * 64 + u * 8];
            *(uint4*)&Vh[r * 72 + u * 8] =
                *(const uint4*)&g_vth[b][r][kb + u * 8];
            *(uint4*)&Vl[r * 72 + u * 8] =
                *(const uint4*)&g_vtl[b][r][kb + u * 8];
        }
        __syncthreads();

        // GEMM1: S = Q K^T (3-term split)
        float s[4][4];
        #pragma unroll
        for (int j = 0; j < 4; j++)
            #pragma unroll
            for (int r = 0; r < 4; r++) s[j][r] = 0.0f;
        #pragma unroll
        for (int kc = 0; kc < 4; kc++) {
            const int cb = kc * 16 + lc;
            #pragma unroll
            for (int j = 0; j < 4; j++) {
                const int sr = wn * 32 + j * 8 + lq;
                uint32_t bh[2], bl[2];
                bh[0] = *(const uint32_t*)&Kh[sr * 72 + cb];
                bh[1] = *(const uint32_t*)&Kh[sr * 72 + cb + 8];
                bl[0] = *(const uint32_t*)&Kl[sr * 72 + cb];
                bl[1] = *(const uint32_t*)&Kl[sr * 72 + cb + 8];
                mma_bf16(s[j], qa_h[kc], bh);
                mma_bf16(s[j], qa_h[kc], bl);
                mma_bf16(s[j], qa_l[kc], bh);
            }
        }

        // scale into log2 domain + causal mask (diag tile = ntile-1)
        if (t == ntile - 1) {
            #pragma unroll
            for (int j = 0; j < 4; j++) {
                const int col = kb + wn * 32 + j * 8 + lc;
                #pragma unroll
                for (int half = 0; half < 2; half++) {
                    const int qrow = q_base + wm * 16 + lq + half * 8;
                    s[j][half * 2 + 0] = (col     <= qrow) ? s[j][half * 2 + 0] * SCALE_L2E : -1e30f;
                    s[j][half * 2 + 1] = (col + 1 <= qrow) ? s[j][half * 2 + 1] * SCALE_L2E : -1e30f;
                }
            }
        } else {
            #pragma unroll
            for (int j = 0; j < 4; j++)
                #pragma unroll
                for (int r = 0; r < 4; r++) s[j][r] *= SCALE_L2E;
        }

        // partial row max (this warp's 32 cols)
        float pm[2] = {-1e30f, -1e30f};
        #pragma unroll
        for (int j = 0; j < 4; j++) {
            pm[0] = fmaxf(pm[0], fmaxf(s[j][0], s[j][1]));
            pm[1] = fmaxf(pm[1], fmaxf(s[j][2], s[j][3]));
        }
        #pragma unroll
        for (int off = 1; off < 4; off <<= 1) {
            pm[0] = fmaxf(pm[0], __shfl_xor_sync(0xffffffffu, pm[0], off));
            pm[1] = fmaxf(pm[1], __shfl_xor_sync(0xffffffffu, pm[1], off));
        }
        if ((lane & 3) == 0) {
            red_max[wn * 32 + wm * 16 + lq]     = pm[0];
            red_max[wn * 32 + wm * 16 + lq + 8] = pm[1];
        }
        __syncthreads();

        // combined max + exp + partial sum + P store
        float mnew[2], alpha[2];
        #pragma unroll
        for (int half = 0; half < 2; half++) {
            const int r = wm * 16 + lq + half * 8;
            const float cm = fmaxf(red_max[r], red_max[32 + r]);
            mnew[half]  = fmaxf(m2[half], cm);
            alpha[half] = exp2_poly(m2[half] - mnew[half]);
            m2[half]    = mnew[half];
        }
        float ps[2] = {0.0f, 0.0f};
        #pragma unroll
        for (int j = 0; j < 4; j++) {
            #pragma unroll
            for (int half = 0; half < 2; half++) {
                float p0 = exp2_poly(s[j][half * 2 + 0] - mnew[half]);
                float p1 = exp2_poly(s[j][half * 2 + 1] - mnew[half]);
                ps[half] += p0 + p1;
                __nv_bfloat16 h0 = __float2bfloat16(p0);
                __nv_bfloat16 h1 = __float2bfloat16(p1);
                const int prow = wm * 16 + lq + half * 8;
                const int pcol = wn * 32 + j * 8 + lc;
                *(uint32_t*)&Ph[prow * 72 + pcol] =
                    (uint32_t)__bfloat16_as_ushort(h0) |
                    ((uint32_t)__bfloat16_as_ushort(h1) << 16);
                *(uint32_t*)&Pl[prow * 72 + pcol] =
                    pack2bf(p0 - __bfloat162float(h0), p1 - __bfloat162float(h1));
            }
        }
        #pragma unroll
        for (int off = 1; off < 4; off <<= 1) {
            ps[0] += __shfl_xor_sync(0xffffffffu, ps[0], off);
            ps[1] += __shfl_xor_sync(0xffffffffu, ps[1], off);
        }
        if ((lane & 3) == 0) {
            red_sum[wn * 32 + wm * 16 + lq]     = ps[0];
            red_sum[wn * 32 + wm * 16 + lq + 8] = ps[1];
        }
        __syncthreads();

        #pragma unroll
        for (int half = 0; half < 2; half++) {
            const int r = wm * 16 + lq + half * 8;
            lsum[half] = lsum[half] * alpha[half] + red_sum[r] + red_sum[32 + r];
        }
        #pragma unroll
        for (int j = 0; j < 4; j++) {
            of[j][0] *= alpha[0]; of[j][1] *= alpha[0];
            of[j][2] *= alpha[1]; of[j][3] *= alpha[1];
        }

        // GEMM2: O += P V (3-term split), V is [h][s] so B frag is direct
        #pragma unroll
        for (int kc = 0; kc < 4; kc++) {
            const int cb = kc * 16 + lc;
            uint32_t ap_h[4], ap_l[4];
            const int rb = wm * 16;
            ap_h[0] = *(const uint32_t*)&Ph[(rb + lq) * 72 + cb];
            ap_h[1] = *(const uint32_t*)&Ph[(rb + lq + 8) * 72 + cb];
            ap_h[2] = *(const uint32_t*)&Ph[(rb + lq) * 72 + cb + 8];
            ap_h[3] = *(const uint32_t*)&Ph[(rb + lq + 8) * 72 + cb + 8];
            ap_l[0] = *(const uint32_t*)&Pl[(rb + lq) * 72 + cb];
            ap_l[1] = *(const uint32_t*)&Pl[(rb + lq + 8) * 72 + cb];
            ap_l[2] = *(const uint32_t*)&Pl[(rb + lq) * 72 + cb + 8];
            ap_l[3] = *(const uint32_t*)&Pl[(rb + lq + 8) * 72 + cb + 8];
            #pragma unroll
            for (int j = 0; j < 4; j++) {
                const int hr = wn * 32 + j * 8 + lq;
                uint32_t bh[2], bl[2];
                bh[0] = *(const uint32_t*)&Vh[hr * 72 + cb];
                bh[1] = *(const uint32_t*)&Vh[hr * 72 + cb + 8];
                bl[0] = *(const uint32_t*)&Vl[hr * 72 + cb];
                bl[1] = *(const uint32_t*)&Vl[hr * 72 + cb + 8];
                mma_bf16(of[j], ap_h, bh);
                mma_bf16(of[j], ap_h, bl);
                mma_bf16(of[j], ap_l, bh);
            }
        }
    }

    // epilogue: store partial (m, l, O_raw)
    const int rowg = b * T_SEQ + q_base + wm * 16 + lq;
    #pragma unroll
    for (int j = 0; j < 4; j++) {
        const int col = wn * 32 + j * 8 + lc;
        *(float2*)&g_po[sp][rowg][col]     = make_float2(of[j][0], of[j][1]);
        *(float2*)&g_po[sp][rowg + 8][col] = make_float2(of[j][2], of[j][3]);
    }
    if (wn == 0 && (lane & 3) == 0) {
        g_pm[sp][rowg]     = m2[0];
        g_pm[sp][rowg + 8] = m2[1];
        g_pl[sp][rowg]     = lsum[0];
        g_pl[sp][rowg + 8] = lsum[1];
    }
}

// ---------------------------------------------------------------------------
// Combine partial splits. block 128 = 2 rows x 64 cols; grid M_TOT/2.
// ---------------------------------------------------------------------------
__global__ __launch_bounds__(128) void combine_kernel(float* __restrict__ out)
{
    const int tid = threadIdx.x;
    const int r = blockIdx.x * 2 + (tid >> 6);
    const int c = tid & 63;
    const int rr = r & (T_SEQ - 1);
    const int qt = rr >> 5;
    const int nsplit = (((qt >> 1) + 1) + TILES_PER_SPLIT - 1) / TILES_PER_SPLIT;

    float M = -1e30f;
    #pragma unroll 4
    for (int s = 0; s < nsplit; s++) M = fmaxf(M, g_pm[s][r]);
    float L = 0.0f, acc = 0.0f;
    #pragma unroll 4
    for (int s = 0; s < nsplit; s++) {
        const float w = exp2_poly(g_pm[s][r] - M);
        L   += w * g_pl[s][r];
        acc += w * g_po[s][r][c];
    }
    out[r * 64 + c] = acc / L;
}

extern "C" void kernel_launch(void* const* d_in, const int* in_sizes, int n_in,
                              void* d_out, int out_size)
{
    const float* x  = (const float*)d_in[0];
    const float* Wq = (const float*)d_in[1];
    const float* Wk = (const float*)d_in[2];
    const float* Wv = (const float*)d_in[3];
    float* out = (float*)d_out;

    split_x_kernel<<<M_TOT * D_IN / 1024, 256>>>(x);
    split_w_kernel<<<3 * 64 * 1024 / 256, 256>>>(Wq, Wk, Wv);
    qkv_mma_kernel<<<M_TOT / 32, 128>>>();
    attn_kernel<<<dim3(64, B_SZ, NSPLIT), 128>>>();
    combine_kernel<<<M_TOT / 2, 128>>>(out);
}

// round 7
// speedup vs baseline: 2.5984x; 1.1305x over previous
#include <cuda_runtime.h>
#include <cuda_bf16.h>
#include <cstdint>

#define D_IN 1024
#define H_SZ 64
#define M_TOT 8192   // B*T
#define T_SEQ 2048
#define B_SZ 4
#define NSPLIT 4
#define TILES_PER_SPLIT 8

// ---------------- global scratch ----------------
__device__ __nv_bfloat16 g_wh[192 * D_IN];     // [w*64+n][k]  (W transposed)
__device__ __nv_bfloat16 g_wl[192 * D_IN];
__device__ __nv_bfloat16 g_qh[M_TOT * H_SZ];   // [global token][h]
__device__ __nv_bfloat16 g_ql[M_TOT * H_SZ];
__device__ __nv_bfloat16 g_kh[M_TOT * H_SZ];
__device__ __nv_bfloat16 g_kl[M_TOT * H_SZ];
__device__ __nv_bfloat16 g_vth[B_SZ][H_SZ][T_SEQ];  // V transposed per batch
__device__ __nv_bfloat16 g_vtl[B_SZ][H_SZ][T_SEQ];
// split-KV partials
__device__ float g_po[NSPLIT][M_TOT][H_SZ];    // unnormalized O
__device__ float g_pm[NSPLIT][M_TOT];          // running max (log2 domain)
__device__ float g_pl[NSPLIT][M_TOT];          // running sum

// ---------------- helpers ----------------
__device__ __forceinline__ void mma_bf16(float d[4], const uint32_t a[4],
                                         const uint32_t b[2]) {
    asm("mma.sync.aligned.m16n8k16.row.col.f32.bf16.bf16.f32 "
        "{%0,%1,%2,%3}, {%4,%5,%6,%7}, {%8,%9}, {%0,%1,%2,%3};\n"
        : "+f"(d[0]), "+f"(d[1]), "+f"(d[2]), "+f"(d[3])
        : "r"(a[0]), "r"(a[1]), "r"(a[2]), "r"(a[3]), "r"(b[0]), "r"(b[1]));
}

__device__ __forceinline__ uint32_t pack2bf(float v0, float v1) {
    unsigned short l = __bfloat16_as_ushort(__float2bfloat16(v0));
    unsigned short h = __bfloat16_as_ushort(__float2bfloat16(v1));
    return (uint32_t)l | ((uint32_t)h << 16);
}

// degree-6 Taylor of 2^x (rel err ~2e-5), FMA pipe only, no MUFU.
__device__ __forceinline__ float exp2_poly(float x) {
    x = fmaxf(x, -126.0f);
    float fl = floorf(x);
    float f  = x - fl;
    float p = 1.5403530e-4f;
    p = fmaf(p, f, 1.3333558e-3f);
    p = fmaf(p, f, 9.6181291e-3f);
    p = fmaf(p, f, 5.5504109e-2f);
    p = fmaf(p, f, 2.4022651e-1f);
    p = fmaf(p, f, 6.9314718e-1f);
    p = fmaf(p, f, 1.0f);
    int e = (int)fl;
    return __int_as_float((e + 127) << 23) * p;
}

// ---------------------------------------------------------------------------
// transpose + split W: [k][n] fp32 -> [w*64+n][k] bf16 hi/lo
// ---------------------------------------------------------------------------
__global__ __launch_bounds__(256) void split_w_kernel(
    const float* __restrict__ Wq, const float* __restrict__ Wk,
    const float* __restrict__ Wv)
{
    const int idx = blockIdx.x * 256 + threadIdx.x;
    const int w = idx >> 16;
    const int n = (idx >> 10) & 63;
    const int k = idx & 1023;
    const float* W = (w == 0) ? Wq : ((w == 1) ? Wk : Wv);
    const float val = W[k * 64 + n];
    __nv_bfloat16 h = __float2bfloat16(val);
    g_wh[idx] = h;
    g_wl[idx] = __float2bfloat16(val - __bfloat162float(h));
}

// ---------------------------------------------------------------------------
// QKV projection via mma.sync bf16 (3-term split) with FUSED x conversion.
// 256 threads, tile M=64, N=192 (q|k|v), K chunks of 32. 128 CTAs.
// Warp grid 2m x 4n: warp = 32 rows (2 m-frags) x 48 cols (6 j).
// ---------------------------------------------------------------------------
__global__ __launch_bounds__(256) void qkv_mma_kernel(const float* __restrict__ x)
{
    __shared__ __align__(16) __nv_bfloat16 xs_h[64][40], xs_l[64][40];
    __shared__ __align__(16) __nv_bfloat16 ws_h[192][40], ws_l[192][40];

    const int tid  = threadIdx.x;
    const int lane = tid & 31;
    const int wid  = tid >> 5;
    const int wm = wid & 1, wn = wid >> 1;   // wn in 0..3
    const int lq = lane >> 2;
    const int lc = (lane & 3) * 2;
    const int m0 = blockIdx.x * 64;

    float d[2][6][4];
    #pragma unroll
    for (int mf = 0; mf < 2; mf++)
        #pragma unroll
        for (int j = 0; j < 6; j++)
            #pragma unroll
            for (int r = 0; r < 4; r++) d[mf][j][r] = 0.0f;

    for (int c = 0; c < 32; c++) {
        const int k0 = c * 32;
        __syncthreads();
        // x tile: 64 rows x 32 k fp32, convert to hi/lo bf16 on the fly.
        // 512 float4 over 256 threads -> 2 each.
        #pragma unroll
        for (int p = 0; p < 2; p++) {
            const int idx = tid + p * 256;
            const int r = idx >> 3, u = idx & 7;   // u: group of 4 floats
            float4 v = *(const float4*)&x[(m0 + r) * D_IN + k0 + u * 4];
            __nv_bfloat16 h0 = __float2bfloat16(v.x);
            __nv_bfloat16 h1 = __float2bfloat16(v.y);
            __nv_bfloat16 h2 = __float2bfloat16(v.z);
            __nv_bfloat16 h3 = __float2bfloat16(v.w);
            uint32_t hi01 = (uint32_t)__bfloat16_as_ushort(h0) |
                            ((uint32_t)__bfloat16_as_ushort(h1) << 16);
            uint32_t hi23 = (uint32_t)__bfloat16_as_ushort(h2) |
                            ((uint32_t)__bfloat16_as_ushort(h3) << 16);
            uint32_t lo01 = pack2bf(v.x - __bfloat162float(h0),
                                    v.y - __bfloat162float(h1));
            uint32_t lo23 = pack2bf(v.z - __bfloat162float(h2),
                                    v.w - __bfloat162float(h3));
            *(uint2*)&xs_h[r][u * 4] = make_uint2(hi01, hi23);
            *(uint2*)&xs_l[r][u * 4] = make_uint2(lo01, lo23);
        }
        // W tiles: 192 rows x 32 k bf16 hi/lo. 768 uint4 over 256 threads -> 3.
        #pragma unroll
        for (int p = 0; p < 3; p++) {
            const int idx = tid + p * 256;
            const int r = idx >> 2, u = idx & 3;
            *(uint4*)&ws_h[r][u * 8] = *(const uint4*)&g_wh[r * D_IN + k0 + u * 8];
            *(uint4*)&ws_l[r][u * 8] = *(const uint4*)&g_wl[r * D_IN + k0 + u * 8];
        }
        __syncthreads();

        #pragma unroll
        for (int kc = 0; kc < 2; kc++) {
            uint32_t ah[2][4], al[2][4];
            const int cb = kc * 16 + lc;
            #pragma unroll
            for (int mf = 0; mf < 2; mf++) {
                const int rb = wm * 32 + mf * 16;
                ah[mf][0] = *(const uint32_t*)&xs_h[rb + lq][cb];
                ah[mf][1] = *(const uint32_t*)&xs_h[rb + lq + 8][cb];
                ah[mf][2] = *(const uint32_t*)&xs_h[rb + lq][cb + 8];
                ah[mf][3] = *(const uint32_t*)&xs_h[rb + lq + 8][cb + 8];
                al[mf][0] = *(const uint32_t*)&xs_l[rb + lq][cb];
                al[mf][1] = *(const uint32_t*)&xs_l[rb + lq + 8][cb];
                al[mf][2] = *(const uint32_t*)&xs_l[rb + lq][cb + 8];
                al[mf][3] = *(const uint32_t*)&xs_l[rb + lq + 8][cb + 8];
            }
            #pragma unroll
            for (int j = 0; j < 6; j++) {
                const int wr = wn * 48 + j * 8 + lq;
                uint32_t bh[2], bl[2];
                bh[0] = *(const uint32_t*)&ws_h[wr][cb];
                bh[1] = *(const uint32_t*)&ws_h[wr][cb + 8];
                bl[0] = *(const uint32_t*)&ws_l[wr][cb];
                bl[1] = *(const uint32_t*)&ws_l[wr][cb + 8];
                #pragma unroll
                for (int mf = 0; mf < 2; mf++) {
                    mma_bf16(d[mf][j], ah[mf], bh);
                    mma_bf16(d[mf][j], ah[mf], bl);
                    mma_bf16(d[mf][j], al[mf], bh);
                }
            }
        }
    }

    // epilogue: hi/lo split + store
    #pragma unroll
    for (int mf = 0; mf < 2; mf++) {
        #pragma unroll
        for (int j = 0; j < 6; j++) {
            const int col = wn * 48 + j * 8 + lc;
            const int mat = col >> 6;
            const int h   = col & 63;
            #pragma unroll
            for (int half = 0; half < 2; half++) {
                const int row = m0 + wm * 32 + mf * 16 + lq + half * 8;
                const float v0 = d[mf][j][half * 2 + 0];
                const float v1 = d[mf][j][half * 2 + 1];
                __nv_bfloat16 h0 = __float2bfloat16(v0);
                __nv_bfloat16 h1 = __float2bfloat16(v1);
                float l0 = v0 - __bfloat162float(h0);
                float l1 = v1 - __bfloat162float(h1);
                if (mat == 0) {
                    *(uint32_t*)&g_qh[row * 64 + h] =
                        (uint32_t)__bfloat16_as_ushort(h0) |
                        ((uint32_t)__bfloat16_as_ushort(h1) << 16);
                    *(uint32_t*)&g_ql[row * 64 + h] = pack2bf(l0, l1);
                } else if (mat == 1) {
                    *(uint32_t*)&g_kh[row * 64 + h] =
                        (uint32_t)__bfloat16_as_ushort(h0) |
                        ((uint32_t)__bfloat16_as_ushort(h1) << 16);
                    *(uint32_t*)&g_kl[row * 64 + h] = pack2bf(l0, l1);
                } else {
                    const int b = row >> 11, t = row & 2047;
                    g_vth[b][h][t]     = h0;
                    g_vth[b][h + 1][t] = h1;
                    g_vtl[b][h][t]     = __float2bfloat16(l0);
                    g_vtl[b][h + 1][t] = __float2bfloat16(l1);
                }
            }
        }
    }
}

// ---------------------------------------------------------------------------
// Split-KV flash attention. grid (64, B, NSPLIT), block 128 (4 warps 2m x 2n).
// Each block processes <= 8 kv tiles and writes partial (m, l, O_raw).
// ---------------------------------------------------------------------------
#define SCALE_L2E 0.18033688f   // 64^-0.5 * log2(e)

__global__ __launch_bounds__(128, 3) void attn_kernel()
{
    const int qt = 63 - blockIdx.x;     // longest-first
    const int ntile = (qt >> 1) + 1;
    const int sp = blockIdx.z;
    const int t0 = sp * TILES_PER_SPLIT;
    if (t0 >= ntile) return;
    const int t1 = min(t0 + TILES_PER_SPLIT, ntile);

    __shared__ __align__(16) char smbuf[46592];
    __nv_bfloat16* Qh = (__nv_bfloat16*)(smbuf + 0);      // [32][72]
    __nv_bfloat16* Ql = (__nv_bfloat16*)(smbuf + 4608);
    __nv_bfloat16* Kh = (__nv_bfloat16*)(smbuf + 9216);   // [64][72]
    __nv_bfloat16* Kl = (__nv_bfloat16*)(smbuf + 18432);
    __nv_bfloat16* Vh = (__nv_bfloat16*)(smbuf + 27648);  // [64][72] (Vt: [h][s])
    __nv_bfloat16* Vl = (__nv_bfloat16*)(smbuf + 36864);
    __nv_bfloat16* Ph = Kh;                               // alias (post-GEMM1)
    __nv_bfloat16* Pl = Kl;
    float* red_max = (float*)(smbuf + 46080);             // [2][32]
    float* red_sum = red_max + 64;                        // [2][32]

    const int tid  = threadIdx.x;
    const int lane = tid & 31;
    const int wid  = tid >> 5;
    const int wm = wid & 1, wn = wid >> 1;
    const int lq = lane >> 2;
    const int lc = (lane & 3) * 2;

    const int b  = blockIdx.y;
    const int q_base = qt * 32;

    const int boff = b * T_SEQ * 64;
    const __nv_bfloat16* qbh = g_qh + boff;
    const __nv_bfloat16* qbl = g_ql + boff;
    const __nv_bfloat16* kbh = g_kh + boff;
    const __nv_bfloat16* kbl = g_kl + boff;

    // load Q tile (hi/lo): 32 rows x 64 h
    #pragma unroll
    for (int p = 0; p < 2; p++) {
        const int idx = tid + p * 128;
        const int r = idx >> 3, u = idx & 7;
        *(uint4*)&Qh[r * 72 + u * 8] =
            *(const uint4*)&qbh[(q_base + r) * 64 + u * 8];
        *(uint4*)&Ql[r * 72 + u * 8] =
            *(const uint4*)&qbl[(q_base + r) * 64 + u * 8];
    }
    __syncthreads();

    // preload Q fragments (loop-invariant)
    uint32_t qa_h[4][4], qa_l[4][4];
    {
        const int rb = wm * 16;
        #pragma unroll
        for (int kc = 0; kc < 4; kc++) {
            const int cb = kc * 16 + lc;
            qa_h[kc][0] = *(const uint32_t*)&Qh[(rb + lq) * 72 + cb];
            qa_h[kc][1] = *(const uint32_t*)&Qh[(rb + lq + 8) * 72 + cb];
            qa_h[kc][2] = *(const uint32_t*)&Qh[(rb + lq) * 72 + cb + 8];
            qa_h[kc][3] = *(const uint32_t*)&Qh[(rb + lq + 8) * 72 + cb + 8];
            qa_l[kc][0] = *(const uint32_t*)&Ql[(rb + lq) * 72 + cb];
            qa_l[kc][1] = *(const uint32_t*)&Ql[(rb + lq + 8) * 72 + cb];
            qa_l[kc][2] = *(const uint32_t*)&Ql[(rb + lq) * 72 + cb + 8];
            qa_l[kc][3] = *(const uint32_t*)&Ql[(rb + lq + 8) * 72 + cb + 8];
        }
    }

    float of[4][4];
    #pragma unroll
    for (int j = 0; j < 4; j++)
        #pragma unroll
        for (int r = 0; r < 4; r++) of[j][r] = 0.0f;
    float m2[2] = {-1e30f, -1e30f};
    float lsum[2] = {0.0f, 0.0f};

    for (int t = t0; t < t1; t++) {
        const int kb = t * 64;
        __syncthreads();   // prior GEMM2 done (Vh/Kh reuse)
        #pragma unroll
        for (int p = 0; p < 4; p++) {
            const int idx = tid + p * 128;
            const int r = idx >> 3, u = idx & 7;
            *(uint4*)&Kh[r * 72 + u * 8] =
                *(const uint4*)&kbh[(kb + r) * 64 + u * 8];
            *(uint4*)&Kl[r * 72 + u * 8] =
                *(const uint4*)&kbl[(kb + r) * 64 + u * 8];
            *(uint4*)&Vh[r * 72 + u * 8] =
                *(const uint4*)&g_vth[b][r][kb + u * 8];
            *(uint4*)&Vl[r * 72 + u * 8] =
                *(const uint4*)&g_vtl[b][r][kb + u * 8];
        }
        __syncthreads();

        // GEMM1: S = Q K^T (3-term split)
        float s[4][4];
        #pragma unroll
        for (int j = 0; j < 4; j++)
            #pragma unroll
            for (int r = 0; r < 4; r++) s[j][r] = 0.0f;
        #pragma unroll
        for (int kc = 0; kc < 4; kc++) {
            const int cb = kc * 16 + lc;
            #pragma unroll
            for (int j = 0; j < 4; j++) {
                const int sr = wn * 32 + j * 8 + lq;
                uint32_t bh[2], bl[2];
                bh[0] = *(const uint32_t*)&Kh[sr * 72 + cb];
                bh[1] = *(const uint32_t*)&Kh[sr * 72 + cb + 8];
                bl[0] = *(const uint32_t*)&Kl[sr * 72 + cb];
                bl[1] = *(const uint32_t*)&Kl[sr * 72 + cb + 8];
                mma_bf16(s[j], qa_h[kc], bh);
                mma_bf16(s[j], qa_h[kc], bl);
                mma_bf16(s[j], qa_l[kc], bh);
            }
        }

        // scale into log2 domain + causal mask (diag tile = ntile-1)
        if (t == ntile - 1) {
            #pragma unroll
            for (int j = 0; j < 4; j++) {
                const int col = kb + wn * 32 + j * 8 + lc;
                #pragma unroll
                for (int half = 0; half < 2; half++) {
                    const int qrow = q_base + wm * 16 + lq + half * 8;
                    s[j][half * 2 + 0] = (col     <= qrow) ? s[j][half * 2 + 0] * SCALE_L2E : -1e30f;
                    s[j][half * 2 + 1] = (col + 1 <= qrow) ? s[j][half * 2 + 1] * SCALE_L2E : -1e30f;
                }
            }
        } else {
            #pragma unroll
            for (int j = 0; j < 4; j++)
                #pragma unroll
                for (int r = 0; r < 4; r++) s[j][r] *= SCALE_L2E;
        }

        // partial row max (this warp's 32 cols)
        float pm[2] = {-1e30f, -1e30f};
        #pragma unroll
        for (int j = 0; j < 4; j++) {
            pm[0] = fmaxf(pm[0], fmaxf(s[j][0], s[j][1]));
            pm[1] = fmaxf(pm[1], fmaxf(s[j][2], s[j][3]));
        }
        #pragma unroll
        for (int off = 1; off < 4; off <<= 1) {
            pm[0] = fmaxf(pm[0], __shfl_xor_sync(0xffffffffu, pm[0], off));
            pm[1] = fmaxf(pm[1], __shfl_xor_sync(0xffffffffu, pm[1], off));
        }
        if ((lane & 3) == 0) {
            red_max[wn * 32 + wm * 16 + lq]     = pm[0];
            red_max[wn * 32 + wm * 16 + lq + 8] = pm[1];
        }
        __syncthreads();

        // combined max + exp + partial sum + P store
        float mnew[2], alpha[2];
        #pragma unroll
        for (int half = 0; half < 2; half++) {
            const int r = wm * 16 + lq + half * 8;
            const float cm = fmaxf(red_max[r], red_max[32 + r]);
            mnew[half]  = fmaxf(m2[half], cm);
            alpha[half] = exp2_poly(m2[half] - mnew[half]);
            m2[half]    = mnew[half];
        }
        float ps[2] = {0.0f, 0.0f};
        #pragma unroll
        for (int j = 0; j < 4; j++) {
            #pragma unroll
            for (int half = 0; half < 2; half++) {
                float p0 = exp2_poly(s[j][half * 2 + 0] - mnew[half]);
                float p1 = exp2_poly(s[j][half * 2 + 1] - mnew[half]);
                ps[half] += p0 + p1;
                __nv_bfloat16 h0 = __float2bfloat16(p0);
                __nv_bfloat16 h1 = __float2bfloat16(p1);
                const int prow = wm * 16 + lq + half * 8;
                const int pcol = wn * 32 + j * 8 + lc;
                *(uint32_t*)&Ph[prow * 72 + pcol] =
                    (uint32_t)__bfloat16_as_ushort(h0) |
                    ((uint32_t)__bfloat16_as_ushort(h1) << 16);
                *(uint32_t*)&Pl[prow * 72 + pcol] =
                    pack2bf(p0 - __bfloat162float(h0), p1 - __bfloat162float(h1));
            }
        }
        #pragma unroll
        for (int off = 1; off < 4; off <<= 1) {
            ps[0] += __shfl_xor_sync(0xffffffffu, ps[0], off);
            ps[1] += __shfl_xor_sync(0xffffffffu, ps[1], off);
        }
        if ((lane & 3) == 0) {
            red_sum[wn * 32 + wm * 16 + lq]     = ps[0];
            red_sum[wn * 32 + wm * 16 + lq + 8] = ps[1];
        }
        __syncthreads();

        #pragma unroll
        for (int half = 0; half < 2; half++) {
            const int r = wm * 16 + lq + half * 8;
            lsum[half] = lsum[half] * alpha[half] + red_sum[r] + red_sum[32 + r];
        }
        #pragma unroll
        for (int j = 0; j < 4; j++) {
            of[j][0] *= alpha[0]; of[j][1] *= alpha[0];
            of[j][2] *= alpha[1]; of[j][3] *= alpha[1];
        }

        // GEMM2: O += P V (3-term split), V is [h][s] so B frag is direct
        #pragma unroll
        for (int kc = 0; kc < 4; kc++) {
            const int cb = kc * 16 + lc;
            uint32_t ap_h[4], ap_l[4];
            const int rb = wm * 16;
            ap_h[0] = *(const uint32_t*)&Ph[(rb + lq) * 72 + cb];
            ap_h[1] = *(const uint32_t*)&Ph[(rb + lq + 8) * 72 + cb];
            ap_h[2] = *(const uint32_t*)&Ph[(rb + lq) * 72 + cb + 8];
            ap_h[3] = *(const uint32_t*)&Ph[(rb + lq + 8) * 72 + cb + 8];
            ap_l[0] = *(const uint32_t*)&Pl[(rb + lq) * 72 + cb];
            ap_l[1] = *(const uint32_t*)&Pl[(rb + lq + 8) * 72 + cb];
            ap_l[2] = *(const uint32_t*)&Pl[(rb + lq) * 72 + cb + 8];
            ap_l[3] = *(const uint32_t*)&Pl[(rb + lq + 8) * 72 + cb + 8];
            #pragma unroll
            for (int j = 0; j < 4; j++) {
                const int hr = wn * 32 + j * 8 + lq;
                uint32_t bh[2], bl[2];
                bh[0] = *(const uint32_t*)&Vh[hr * 72 + cb];
                bh[1] = *(const uint32_t*)&Vh[hr * 72 + cb + 8];
                bl[0] = *(const uint32_t*)&Vl[hr * 72 + cb];
                bl[1] = *(const uint32_t*)&Vl[hr * 72 + cb + 8];
                mma_bf16(of[j], ap_h, bh);
                mma_bf16(of[j], ap_h, bl);
                mma_bf16(of[j], ap_l, bh);
            }
        }
    }

    // epilogue: store partial (m, l, O_raw)
    const int rowg = b * T_SEQ + q_base + wm * 16 + lq;
    #pragma unroll
    for (int j = 0; j < 4; j++) {
        const int col = wn * 32 + j * 8 + lc;
        *(float2*)&g_po[sp][rowg][col]     = make_float2(of[j][0], of[j][1]);
        *(float2*)&g_po[sp][rowg + 8][col] = make_float2(of[j][2], of[j][3]);
    }
    if (wn == 0 && (lane & 3) == 0) {
        g_pm[sp][rowg]     = m2[0];
        g_pm[sp][rowg + 8] = m2[1];
        g_pl[sp][rowg]     = lsum[0];
        g_pl[sp][rowg + 8] = lsum[1];
    }
}

// ---------------------------------------------------------------------------
// Combine partial splits. block 128 = 2 rows x 64 cols; grid M_TOT/2.
// ---------------------------------------------------------------------------
__global__ __launch_bounds__(128) void combine_kernel(float* __restrict__ out)
{
    const int tid = threadIdx.x;
    const int r = blockIdx.x * 2 + (tid >> 6);
    const int c = tid & 63;
    const int rr = r & (T_SEQ - 1);
    const int qt = rr >> 5;
    const int nsplit = (((qt >> 1) + 1) + TILES_PER_SPLIT - 1) / TILES_PER_SPLIT;

    float M = -1e30f;
    #pragma unroll 4
    for (int s = 0; s < nsplit; s++) M = fmaxf(M, g_pm[s][r]);
    float L = 0.0f, acc = 0.0f;
    #pragma unroll 4
    for (int s = 0; s < nsplit; s++) {
        const float w = exp2_poly(g_pm[s][r] - M);
        L   += w * g_pl[s][r];
        acc += w * g_po[s][r][c];
    }
    out[r * 64 + c] = acc / L;
}

extern "C" void kernel_launch(void* const* d_in, const int* in_sizes, int n_in,
                              void* d_out, int out_size)
{
    const float* x  = (const float*)d_in[0];
    const float* Wq = (const float*)d_in[1];
    const float* Wk = (const float*)d_in[2];
    const float* Wv = (const float*)d_in[3];
    float* out = (float*)d_out;

    split_w_kernel<<<3 * 64 * 1024 / 256, 256>>>(Wq, Wk, Wv);
    qkv_mma_kernel<<<M_TOT / 64, 256>>>(x);
    attn_kernel<<<dim3(64, B_SZ, NSPLIT), 128>>>();
    combine_kernel<<<M_TOT / 2, 128>>>(out);
}

// round 8
// speedup vs baseline: 2.7375x; 1.0535x over previous
#include <cuda_runtime.h>
#include <cuda_bf16.h>
#include <cstdint>

#define D_IN 1024
#define H_SZ 64
#define M_TOT 8192   // B*T
#define T_SEQ 2048
#define B_SZ 4
#define NSPLIT 4
#define TILES_PER_SPLIT 8
#define QTILES 32            // T_SEQ / 64

// ---------------- global scratch ----------------
__device__ __nv_bfloat16 g_wh[192 * D_IN];     // [w*64+n][k]  (W transposed)
__device__ __nv_bfloat16 g_wl[192 * D_IN];
__device__ __nv_bfloat16 g_qh[M_TOT * H_SZ];   // [global token][h]
__device__ __nv_bfloat16 g_ql[M_TOT * H_SZ];
__device__ __nv_bfloat16 g_kh[M_TOT * H_SZ];
__device__ __nv_bfloat16 g_kl[M_TOT * H_SZ];
__device__ __nv_bfloat16 g_vth[B_SZ][H_SZ][T_SEQ];  // V transposed per batch
__device__ __nv_bfloat16 g_vtl[B_SZ][H_SZ][T_SEQ];
// split-KV partials
__device__ float g_po[NSPLIT][M_TOT][H_SZ];    // unnormalized O
__device__ float g_pm[NSPLIT][M_TOT];          // running max (log2 domain)
__device__ float g_pl[NSPLIT][M_TOT];          // running sum

// ---------------- helpers ----------------
__device__ __forceinline__ void mma_bf16(float d[4], const uint32_t a[4],
                                         const uint32_t b[2]) {
    asm("mma.sync.aligned.m16n8k16.row.col.f32.bf16.bf16.f32 "
        "{%0,%1,%2,%3}, {%4,%5,%6,%7}, {%8,%9}, {%0,%1,%2,%3};\n"
        : "+f"(d[0]), "+f"(d[1]), "+f"(d[2]), "+f"(d[3])
        : "r"(a[0]), "r"(a[1]), "r"(a[2]), "r"(a[3]), "r"(b[0]), "r"(b[1]));
}

__device__ __forceinline__ uint32_t pack2bf(float v0, float v1) {
    unsigned short l = __bfloat16_as_ushort(__float2bfloat16(v0));
    unsigned short h = __bfloat16_as_ushort(__float2bfloat16(v1));
    return (uint32_t)l | ((uint32_t)h << 16);
}

// split pair into hi (packed bf16x2) + lo residual (packed bf16x2)
__device__ __forceinline__ void split_pair(float x, float y,
                                           uint32_t& hi, uint32_t& lo) {
    __nv_bfloat16 hx = __float2bfloat16(x);
    __nv_bfloat16 hy = __float2bfloat16(y);
    hi = (uint32_t)__bfloat16_as_ushort(hx) |
         ((uint32_t)__bfloat16_as_ushort(hy) << 16);
    lo = pack2bf(x - __bfloat162float(hx), y - __bfloat162float(hy));
}

// degree-6 Taylor of 2^x (rel err ~2e-5), FMA pipe only, no MUFU.
__device__ __forceinline__ float exp2_poly(float x) {
    x = fmaxf(x, -126.0f);
    float fl = floorf(x);
    float f  = x - fl;
    float p = 1.5403530e-4f;
    p = fmaf(p, f, 1.3333558e-3f);
    p = fmaf(p, f, 9.6181291e-3f);
    p = fmaf(p, f, 5.5504109e-2f);
    p = fmaf(p, f, 2.4022651e-1f);
    p = fmaf(p, f, 6.9314718e-1f);
    p = fmaf(p, f, 1.0f);
    int e = (int)fl;
    return __int_as_float((e + 127) << 23) * p;
}

#define CP_ASYNC16(dst, src) \
    asm volatile("cp.async.cg.shared.global [%0], [%1], 16;" \
                 :: "r"(dst), "l"(src) : "memory")
#define CP_COMMIT() asm volatile("cp.async.commit_group;" ::: "memory")
#define CP_WAIT1()  asm volatile("cp.async.wait_group 1;" ::: "memory")
#define CP_WAIT0()  asm volatile("cp.async.wait_group 0;" ::: "memory")

// ---------------------------------------------------------------------------
// transpose + split W: [k][n] fp32 -> [w*64+n][k] bf16 hi/lo
// ---------------------------------------------------------------------------
__global__ __launch_bounds__(256) void split_w_kernel(
    const float* __restrict__ Wq, const float* __restrict__ Wk,
    const float* __restrict__ Wv)
{
    const int idx = blockIdx.x * 256 + threadIdx.x;
    const int w = idx >> 16;
    const int n = (idx >> 10) & 63;
    const int k = idx & 1023;
    const float* W = (w == 0) ? Wq : ((w == 1) ? Wk : Wv);
    const float val = W[k * 64 + n];
    __nv_bfloat16 h = __float2bfloat16(val);
    g_wh[idx] = h;
    g_wl[idx] = __float2bfloat16(val - __bfloat162float(h));
}

// ---------------------------------------------------------------------------
// QKV projection via mma.sync bf16 (3-term split) with fused x conversion.
// 256 threads, tile M=64, N=192 (q|k|v), K chunks of 32. 128 CTAs. (R7, kept)
// ---------------------------------------------------------------------------
__global__ __launch_bounds__(256) void qkv_mma_kernel(const float* __restrict__ x)
{
    __shared__ __align__(16) __nv_bfloat16 xs_h[64][40], xs_l[64][40];
    __shared__ __align__(16) __nv_bfloat16 ws_h[192][40], ws_l[192][40];

    const int tid  = threadIdx.x;
    const int lane = tid & 31;
    const int wid  = tid >> 5;
    const int wm = wid & 1, wn = wid >> 1;
    const int lq = lane >> 2;
    const int lc = (lane & 3) * 2;
    const int m0 = blockIdx.x * 64;

    float d[2][6][4];
    #pragma unroll
    for (int mf = 0; mf < 2; mf++)
        #pragma unroll
        for (int j = 0; j < 6; j++)
            #pragma unroll
            for (int r = 0; r < 4; r++) d[mf][j][r] = 0.0f;

    for (int c = 0; c < 32; c++) {
        const int k0 = c * 32;
        __syncthreads();
        #pragma unroll
        for (int p = 0; p < 2; p++) {
            const int idx = tid + p * 256;
            const int r = idx >> 3, u = idx & 7;
            float4 v = *(const float4*)&x[(m0 + r) * D_IN + k0 + u * 4];
            uint32_t hi01, lo01, hi23, lo23;
            split_pair(v.x, v.y, hi01, lo01);
            split_pair(v.z, v.w, hi23, lo23);
            *(uint2*)&xs_h[r][u * 4] = make_uint2(hi01, hi23);
            *(uint2*)&xs_l[r][u * 4] = make_uint2(lo01, lo23);
        }
        #pragma unroll
        for (int p = 0; p < 3; p++) {
            const int idx = tid + p * 256;
            const int r = idx >> 2, u = idx & 3;
            *(uint4*)&ws_h[r][u * 8] = *(const uint4*)&g_wh[r * D_IN + k0 + u * 8];
            *(uint4*)&ws_l[r][u * 8] = *(const uint4*)&g_wl[r * D_IN + k0 + u * 8];
        }
        __syncthreads();

        #pragma unroll
        for (int kc = 0; kc < 2; kc++) {
            uint32_t ah[2][4], al[2][4];
            const int cb = kc * 16 + lc;
            #pragma unroll
            for (int mf = 0; mf < 2; mf++) {
                const int rb = wm * 32 + mf * 16;
                ah[mf][0] = *(const uint32_t*)&xs_h[rb + lq][cb];
                ah[mf][1] = *(const uint32_t*)&xs_h[rb + lq + 8][cb];
                ah[mf][2] = *(const uint32_t*)&xs_h[rb + lq][cb + 8];
                ah[mf][3] = *(const uint32_t*)&xs_h[rb + lq + 8][cb + 8];
                al[mf][0] = *(const uint32_t*)&xs_l[rb + lq][cb];
                al[mf][1] = *(const uint32_t*)&xs_l[rb + lq + 8][cb];
                al[mf][2] = *(const uint32_t*)&xs_l[rb + lq][cb + 8];
                al[mf][3] = *(const uint32_t*)&xs_l[rb + lq + 8][cb + 8];
            }
            #pragma unroll
            for (int j = 0; j < 6; j++) {
                const int wr = wn * 48 + j * 8 + lq;
                uint32_t bh[2], bl[2];
                bh[0] = *(const uint32_t*)&ws_h[wr][cb];
                bh[1] = *(const uint32_t*)&ws_h[wr][cb + 8];
                bl[0] = *(const uint32_t*)&ws_l[wr][cb];
                bl[1] = *(const uint32_t*)&ws_l[wr][cb + 8];
                #pragma unroll
                for (int mf = 0; mf < 2; mf++) {
                    mma_bf16(d[mf][j], ah[mf], bh);
                    mma_bf16(d[mf][j], ah[mf], bl);
                    mma_bf16(d[mf][j], al[mf], bh);
                }
            }
        }
    }

    #pragma unroll
    for (int mf = 0; mf < 2; mf++) {
        #pragma unroll
        for (int j = 0; j < 6; j++) {
            const int col = wn * 48 + j * 8 + lc;
            const int mat = col >> 6;
            const int h   = col & 63;
            #pragma unroll
            for (int half = 0; half < 2; half++) {
                const int row = m0 + wm * 32 + mf * 16 + lq + half * 8;
                const float v0 = d[mf][j][half * 2 + 0];
                const float v1 = d[mf][j][half * 2 + 1];
                uint32_t hi, lo;
                split_pair(v0, v1, hi, lo);
                if (mat == 0) {
                    *(uint32_t*)&g_qh[row * 64 + h] = hi;
                    *(uint32_t*)&g_ql[row * 64 + h] = lo;
                } else if (mat == 1) {
                    *(uint32_t*)&g_kh[row * 64 + h] = hi;
                    *(uint32_t*)&g_kl[row * 64 + h] = lo;
                } else {
                    const int b = row >> 11, t = row & 2047;
                    __nv_bfloat16 h0 = __float2bfloat16(v0);
                    __nv_bfloat16 h1 = __float2bfloat16(v1);
                    g_vth[b][h][t]     = h0;
                    g_vth[b][h + 1][t] = h1;
                    g_vtl[b][h][t]     = __float2bfloat16(v0 - __bfloat162float(h0));
                    g_vtl[b][h + 1][t] = __float2bfloat16(v1 - __bfloat162float(h1));
                }
            }
        }
    }
}

// ---------------------------------------------------------------------------
// FA2-style split-KV flash attention. BQ=64, BK=64, 128 threads (4 warps).
// Warp w owns q-rows [w*16, w*16+16) x ALL 64 kv cols: softmax = quad shfl,
// P stays in registers. K/V double-buffered via cp.async. Q aliases stage 0.
// smem: 2 stages x (Kh|Kl|Vh|Vl)[64][72] = 73728 B dynamic.
// ---------------------------------------------------------------------------
#define SCALE_L2E 0.18033688f   // 64^-0.5 * log2(e)
#define STAGE_BYTES 36864
#define ARR_BYTES   9216        // 64*72*2

__global__ __launch_bounds__(128, 3) void attn_kernel()
{
    const int qt = (QTILES - 1) - blockIdx.x;   // longest-first
    const int ntile = qt + 1;
    const int sp = blockIdx.z;
    const int t0 = sp * TILES_PER_SPLIT;
    if (t0 >= ntile) return;
    const int t1 = min(t0 + TILES_PER_SPLIT, ntile);

    extern __shared__ __align__(16) char smbuf[];
    const uint32_t smbase = (uint32_t)__cvta_generic_to_shared(smbuf);

    const int tid  = threadIdx.x;
    const int lane = tid & 31;
    const int warp = tid >> 5;
    const int lq = lane >> 2;
    const int lc = (lane & 3) * 2;

    const int b  = blockIdx.y;
    const int q_base = qt * 64;
    const int boff = b * T_SEQ * 64;
    const __nv_bfloat16* qbh = g_qh + boff;
    const __nv_bfloat16* qbl = g_ql + boff;
    const __nv_bfloat16* kbh = g_kh + boff;
    const __nv_bfloat16* kbl = g_kl + boff;

    // ---- load Q into stage-0 smem (64x64 hi/lo), extract frags, release ----
    {
        __nv_bfloat16* Qh = (__nv_bfloat16*)(smbuf);
        __nv_bfloat16* Ql = (__nv_bfloat16*)(smbuf + ARR_BYTES);
        #pragma unroll
        for (int p = 0; p < 4; p++) {
            const int idx = tid + p * 128;
            const int r = idx >> 3, u = idx & 7;
            *(uint4*)&Qh[r * 72 + u * 8] =
                *(const uint4*)&qbh[(q_base + r) * 64 + u * 8];
            *(uint4*)&Ql[r * 72 + u * 8] =
                *(const uint4*)&qbl[(q_base + r) * 64 + u * 8];
        }
    }
    __syncthreads();
    uint32_t qa_h[4][4], qa_l[4][4];
    {
        const __nv_bfloat16* Qh = (const __nv_bfloat16*)(smbuf);
        const __nv_bfloat16* Ql = (const __nv_bfloat16*)(smbuf + ARR_BYTES);
        const int rb = warp * 16;
        #pragma unroll
        for (int kc = 0; kc < 4; kc++) {
            const int cb = kc * 16 + lc;
            qa_h[kc][0] = *(const uint32_t*)&Qh[(rb + lq) * 72 + cb];
            qa_h[kc][1] = *(const uint32_t*)&Qh[(rb + lq + 8) * 72 + cb];
            qa_h[kc][2] = *(const uint32_t*)&Qh[(rb + lq) * 72 + cb + 8];
            qa_h[kc][3] = *(const uint32_t*)&Qh[(rb + lq + 8) * 72 + cb + 8];
            qa_l[kc][0] = *(const uint32_t*)&Ql[(rb + lq) * 72 + cb];
            qa_l[kc][1] = *(const uint32_t*)&Ql[(rb + lq + 8) * 72 + cb];
            qa_l[kc][2] = *(const uint32_t*)&Ql[(rb + lq) * 72 + cb + 8];
            qa_l[kc][3] = *(const uint32_t*)&Ql[(rb + lq + 8) * 72 + cb + 8];
        }
    }
    __syncthreads();

    // ---- prefetch helper (lambda-style macro body) ----
    // each thread: 4 rows-slices x 4 arrays of 16B
    #define PREFETCH(stage, kb_)                                                 \
    do {                                                                         \
        const uint32_t stoff = smbase + (stage) * STAGE_BYTES;                   \
        _Pragma("unroll")                                                        \
        for (int p = 0; p < 4; p++) {                                            \
            const int idx = tid + p * 128;                                       \
            const int r = idx >> 3, u = idx & 7;                                 \
            const uint32_t o = stoff + r * 144 + u * 16;                         \
            CP_ASYNC16(o,                  &kbh[((kb_) + r) * 64 + u * 8]);      \
            CP_ASYNC16(o + ARR_BYTES,      &kbl[((kb_) + r) * 64 + u * 8]);      \
            CP_ASYNC16(o + 2 * ARR_BYTES,  &g_vth[b][r][(kb_) + u * 8]);         \
            CP_ASYNC16(o + 3 * ARR_BYTES,  &g_vtl[b][r][(kb_) + u * 8]);         \
        }                                                                        \
    } while (0)

    PREFETCH(0, t0 * 64);
    CP_COMMIT();

    float of[8][4];
    #pragma unroll
    for (int j = 0; j < 8; j++)
        #pragma unroll
        for (int r = 0; r < 4; r++) of[j][r] = 0.0f;
    float m2[2] = {-1e30f, -1e30f};
    float lsum[2] = {0.0f, 0.0f};

    int buf = 0;
    for (int t = t0; t < t1; t++) {
        const int kb = t * 64;
        const bool more = (t + 1 < t1);
        if (more) { PREFETCH(buf ^ 1, (t + 1) * 64); CP_COMMIT(); }
        if (more) CP_WAIT1(); else CP_WAIT0();
        __syncthreads();

        const __nv_bfloat16* Kh = (const __nv_bfloat16*)(smbuf + buf * STAGE_BYTES);
        const __nv_bfloat16* Kl = Kh + ARR_BYTES / 2;
        const __nv_bfloat16* Vh = Kh + ARR_BYTES;
        const __nv_bfloat16* Vl = Kh + 3 * ARR_BYTES / 2;

        // GEMM1: S = Q K^T (3-term split), full 64 cols per warp
        float s[8][4];
        #pragma unroll
        for (int j = 0; j < 8; j++)
            #pragma unroll
            for (int r = 0; r < 4; r++) s[j][r] = 0.0f;
        #pragma unroll
        for (int kc = 0; kc < 4; kc++) {
            const int cb = kc * 16 + lc;
            #pragma unroll
            for (int j = 0; j < 8; j++) {
                const int sr = j * 8 + lq;
                uint32_t bh[2], bl[2];
                bh[0] = *(const uint32_t*)&Kh[sr * 72 + cb];
                bh[1] = *(const uint32_t*)&Kh[sr * 72 + cb + 8];
                bl[0] = *(const uint32_t*)&Kl[sr * 72 + cb];
                bl[1] = *(const uint32_t*)&Kl[sr * 72 + cb + 8];
                mma_bf16(s[j], qa_h[kc], bh);
                mma_bf16(s[j], qa_h[kc], bl);
                mma_bf16(s[j], qa_l[kc], bh);
            }
        }

        // scale + causal mask (diagonal tile only)
        if (t == qt) {
            #pragma unroll
            for (int j = 0; j < 8; j++) {
                const int col = kb + j * 8 + lc;
                #pragma unroll
                for (int half = 0; half < 2; half++) {
                    const int qrow = q_base + warp * 16 + lq + half * 8;
                    s[j][half * 2 + 0] = (col     <= qrow) ? s[j][half * 2 + 0] * SCALE_L2E : -1e30f;
                    s[j][half * 2 + 1] = (col + 1 <= qrow) ? s[j][half * 2 + 1] * SCALE_L2E : -1e30f;
                }
            }
        } else {
            #pragma unroll
            for (int j = 0; j < 8; j++)
                #pragma unroll
                for (int r = 0; r < 4; r++) s[j][r] *= SCALE_L2E;
        }

        // row stats entirely in-warp (quad shuffles)
        float pm[2] = {-1e30f, -1e30f};
        #pragma unroll
        for (int j = 0; j < 8; j++) {
            pm[0] = fmaxf(pm[0], fmaxf(s[j][0], s[j][1]));
            pm[1] = fmaxf(pm[1], fmaxf(s[j][2], s[j][3]));
        }
        pm[0] = fmaxf(pm[0], __shfl_xor_sync(0xffffffffu, pm[0], 1));
        pm[1] = fmaxf(pm[1], __shfl_xor_sync(0xffffffffu, pm[1], 1));
        pm[0] = fmaxf(pm[0], __shfl_xor_sync(0xffffffffu, pm[0], 2));
        pm[1] = fmaxf(pm[1], __shfl_xor_sync(0xffffffffu, pm[1], 2));

        float mnew[2], alpha[2];
        #pragma unroll
        for (int half = 0; half < 2; half++) {
            mnew[half]  = fmaxf(m2[half], pm[half]);
            alpha[half] = exp2_poly(m2[half] - mnew[half]);
            m2[half]    = mnew[half];
        }
        float ps[2] = {0.0f, 0.0f};
        #pragma unroll
        for (int j = 0; j < 8; j++) {
            s[j][0] = exp2_poly(s[j][0] - mnew[0]);
            s[j][1] = exp2_poly(s[j][1] - mnew[0]);
            s[j][2] = exp2_poly(s[j][2] - mnew[1]);
            s[j][3] = exp2_poly(s[j][3] - mnew[1]);
            ps[0] += s[j][0] + s[j][1];
            ps[1] += s[j][2] + s[j][3];
        }
        ps[0] += __shfl_xor_sync(0xffffffffu, ps[0], 1);
        ps[1] += __shfl_xor_sync(0xffffffffu, ps[1], 1);
        ps[0] += __shfl_xor_sync(0xffffffffu, ps[0], 2);
        ps[1] += __shfl_xor_sync(0xffffffffu, ps[1], 2);

        lsum[0] = lsum[0] * alpha[0] + ps[0];
        lsum[1] = lsum[1] * alpha[1] + ps[1];
        #pragma unroll
        for (int j = 0; j < 8; j++) {
            of[j][0] *= alpha[0]; of[j][1] *= alpha[0];
            of[j][2] *= alpha[1]; of[j][3] *= alpha[1];
        }

        // GEMM2: O += P V  (P hi/lo built in registers from s)
        #pragma unroll
        for (int kc = 0; kc < 4; kc++) {
            const int cb = kc * 16 + lc;
            uint32_t ap_h[4], ap_l[4];
            split_pair(s[2 * kc][0],     s[2 * kc][1],     ap_h[0], ap_l[0]);
            split_pair(s[2 * kc][2],     s[2 * kc][3],     ap_h[1], ap_l[1]);
            split_pair(s[2 * kc + 1][0], s[2 * kc + 1][1], ap_h[2], ap_l[2]);
            split_pair(s[2 * kc + 1][2], s[2 * kc + 1][3], ap_h[3], ap_l[3]);
            #pragma unroll
            for (int j = 0; j < 8; j++) {
                const int hr = j * 8 + lq;
                uint32_t bh[2], bl[2];
                bh[0] = *(const uint32_t*)&Vh[hr * 72 + cb];
                bh[1] = *(const uint32_t*)&Vh[hr * 72 + cb + 8];
                bl[0] = *(const uint32_t*)&Vl[hr * 72 + cb];
                bl[1] = *(const uint32_t*)&Vl[hr * 72 + cb + 8];
                mma_bf16(of[j], ap_h, bh);
                mma_bf16(of[j], ap_h, bl);
                mma_bf16(of[j], ap_l, bh);
            }
        }
        __syncthreads();
        buf ^= 1;
    }

    // epilogue: store partial (m, l, O_raw)
    const int rowg = b * T_SEQ + q_base + warp * 16 + lq;
    #pragma unroll
    for (int j = 0; j < 8; j++) {
        const int col = j * 8 + lc;
        *(float2*)&g_po[sp][rowg][col]     = make_float2(of[j][0], of[j][1]);
        *(float2*)&g_po[sp][rowg + 8][col] = make_float2(of[j][2], of[j][3]);
    }
    if ((lane & 3) == 0) {
        g_pm[sp][rowg]     = m2[0];
        g_pm[sp][rowg + 8] = m2[1];
        g_pl[sp][rowg]     = lsum[0];
        g_pl[sp][rowg + 8] = lsum[1];
    }
}

// ---------------------------------------------------------------------------
// Combine partial splits. block 128 = 2 rows x 64 cols; grid M_TOT/2.
// ---------------------------------------------------------------------------
__global__ __launch_bounds__(128) void combine_kernel(float* __restrict__ out)
{
    const int tid = threadIdx.x;
    const int r = blockIdx.x * 2 + (tid >> 6);
    const int c = tid & 63;
    const int rr = r & (T_SEQ - 1);
    const int qt = rr >> 6;                       // 64-row q tiles now
    const int nsplit = ((qt + 1) + TILES_PER_SPLIT - 1) / TILES_PER_SPLIT;

    float M = -1e30f;
    #pragma unroll 4
    for (int s = 0; s < nsplit; s++) M = fmaxf(M, g_pm[s][r]);
    float L = 0.0f, acc = 0.0f;
    #pragma unroll 4
    for (int s = 0; s < nsplit; s++) {
        const float w = exp2_poly(g_pm[s][r] - M);
        L   += w * g_pl[s][r];
        acc += w * g_po[s][r][c];
    }
    out[r * 64 + c] = acc / L;
}

extern "C" void kernel_launch(void* const* d_in, const int* in_sizes, int n_in,
                              void* d_out, int out_size)
{
    const float* x  = (const float*)d_in[0];
    const float* Wq = (const float*)d_in[1];
    const float* Wk = (const float*)d_in[2];
    const float* Wv = (const float*)d_in[3];
    float* out = (float*)d_out;

    cudaFuncSetAttribute(attn_kernel,
                         cudaFuncAttributeMaxDynamicSharedMemorySize,
                         2 * STAGE_BYTES);

    split_w_kernel<<<3 * 64 * 1024 / 256, 256>>>(Wq, Wk, Wv);
    qkv_mma_kernel<<<M_TOT / 64, 256>>>(x);
    attn_kernel<<<dim3(QTILES, B_SZ, NSPLIT), 128, 2 * STAGE_BYTES>>>();
    combine_kernel<<<M_TOT / 2, 128>>>(out);
}